// round 5
// baseline (speedup 1.0000x reference)
#include <cuda_runtime.h>

// ---------------------------------------------------------------------------
// EncoderLayer: B=4 S=2048 D=1024 H=16 dk=64 Dff=4096, fp32.
// Pipeline:
//   Q = (x@Wq)*0.125 ; K = x@Wk ; V = x@Wv          (sgemm)
//   ctx = flash_attention(Q,K,V,mask)               (attn kernel)
//   t1  = ctx@Wo + x                                (sgemm, residual epilogue)
//   h   = LN1(t1)
//   ff  = relu(h@W1 + b1)                           (sgemm, bias+relu)
//   t1  = ff@W2 + b2 + h                            (sgemm, bias+residual)
//   out = LN2(t1)
// ---------------------------------------------------------------------------

constexpr int NB  = 4;
constexpr int SEQ = 2048;
constexpr int DIM = 1024;
constexpr int NH  = 16;
constexpr int DK  = 64;
constexpr int DFF = 4096;
constexpr int TOK = NB * SEQ;          // 8192

// scratch (device-global arrays: allocation-free per harness rules)
__device__ float g_Q  [TOK * DIM];
__device__ float g_K  [TOK * DIM];
__device__ float g_V  [TOK * DIM];
__device__ float g_ctx[TOK * DIM];
__device__ float g_t1 [TOK * DIM];
__device__ float g_h  [TOK * DIM];
__device__ float g_ff [(size_t)TOK * DFF];

// ---------------------------------------------------------------------------
// SGEMM: C[M,N] = epilogue(alpha * A[M,K] @ B[K,N])
// 128x128 block tile, BK=16, 256 threads, 8x8 per-thread microtile.
// ---------------------------------------------------------------------------
template<bool BIAS, bool RELU, bool RES>
__global__ __launch_bounds__(256, 2)
void sgemm(const float* __restrict__ A, const float* __restrict__ Bw,
           const float* __restrict__ bias, const float* __restrict__ res,
           float* __restrict__ C, int M, int N, int K, float alpha)
{
    __shared__ float As[16][128];   // [k][m]  (A stored transposed)
    __shared__ float Bs[16][128];   // [k][n]

    const int tid  = threadIdx.x;
    const int tx   = tid & 15;
    const int ty   = tid >> 4;
    const int row0 = blockIdx.y * 128;
    const int col0 = blockIdx.x * 128;

    const int la_r = tid >> 2;          // 0..63
    const int la_c = (tid & 3) * 4;     // 0,4,8,12
    const int lb_r = tid >> 5;          // 0..7
    const int lb_c = (tid & 31) * 4;    // 0..124

    float acc[8][8];
#pragma unroll
    for (int i = 0; i < 8; ++i)
#pragma unroll
        for (int j = 0; j < 8; ++j) acc[i][j] = 0.f;

    const float* Ap = A  + (size_t)row0 * K;
    const float* Bp = Bw + col0;

    for (int k0 = 0; k0 < K; k0 += 16) {
        float4 a0 = *(const float4*)&Ap[(size_t)(la_r     ) * K + k0 + la_c];
        float4 a1 = *(const float4*)&Ap[(size_t)(la_r + 64) * K + k0 + la_c];
        float4 b0 = *(const float4*)&Bp[(size_t)(k0 + lb_r    ) * N + lb_c];
        float4 b1 = *(const float4*)&Bp[(size_t)(k0 + lb_r + 8) * N + lb_c];
        __syncthreads();
        As[la_c + 0][la_r] = a0.x;
        As[la_c + 1][la_r] = a0.y;
        As[la_c + 2][la_r] = a0.z;
        As[la_c + 3][la_r] = a0.w;
        As[la_c + 0][la_r + 64] = a1.x;
        As[la_c + 1][la_r + 64] = a1.y;
        As[la_c + 2][la_r + 64] = a1.z;
        As[la_c + 3][la_r + 64] = a1.w;
        *(float4*)&Bs[lb_r    ][lb_c] = b0;
        *(float4*)&Bs[lb_r + 8][lb_c] = b1;
        __syncthreads();
#pragma unroll
        for (int kk = 0; kk < 16; ++kk) {
            float4 ra0 = *(const float4*)&As[kk][ty * 8];
            float4 ra1 = *(const float4*)&As[kk][ty * 8 + 4];
            float4 rb0 = *(const float4*)&Bs[kk][tx * 8];
            float4 rb1 = *(const float4*)&Bs[kk][tx * 8 + 4];
            float ar[8] = {ra0.x, ra0.y, ra0.z, ra0.w, ra1.x, ra1.y, ra1.z, ra1.w};
            float br[8] = {rb0.x, rb0.y, rb0.z, rb0.w, rb1.x, rb1.y, rb1.z, rb1.w};
#pragma unroll
            for (int i = 0; i < 8; ++i)
#pragma unroll
                for (int j = 0; j < 8; ++j)
                    acc[i][j] = fmaf(ar[i], br[j], acc[i][j]);
        }
    }

#pragma unroll
    for (int i = 0; i < 8; ++i) {
        const size_t r = (size_t)(row0 + ty * 8 + i);
#pragma unroll
        for (int j4 = 0; j4 < 8; j4 += 4) {
            const int c = col0 + tx * 8 + j4;
            float4 v;
            v.x = acc[i][j4 + 0] * alpha;
            v.y = acc[i][j4 + 1] * alpha;
            v.z = acc[i][j4 + 2] * alpha;
            v.w = acc[i][j4 + 3] * alpha;
            if (BIAS) {
                const float4 bb = *(const float4*)&bias[c];
                v.x += bb.x; v.y += bb.y; v.z += bb.z; v.w += bb.w;
            }
            if (RES) {
                const float4 rr = *(const float4*)&res[r * N + c];
                v.x += rr.x; v.y += rr.y; v.z += rr.z; v.w += rr.w;
            }
            if (RELU) {
                v.x = fmaxf(v.x, 0.f); v.y = fmaxf(v.y, 0.f);
                v.z = fmaxf(v.z, 0.f); v.w = fmaxf(v.w, 0.f);
            }
            *(float4*)&C[r * N + c] = v;
        }
    }
}

// ---------------------------------------------------------------------------
// Flash attention, fp32. Grid: (SEQ/128, NB*NH). 256 threads.
// BM=128 queries, BN=64 keys per tile, dk=64. 1/sqrt(dk) pre-folded into Q.
// Dynamic smem layout (floats):
//   Qs[64][132]  (dk-major, transposed)   Ks[64][68] (dk-major)
//   Vs[64][68]   (key-major, natural)     Ps[64][132] (key-major, transposed)
// ---------------------------------------------------------------------------
constexpr int ATT_SMEM_FLOATS = 64 * 132 + 64 * 68 + 64 * 68 + 64 * 132;
constexpr int ATT_SMEM_BYTES  = ATT_SMEM_FLOATS * 4;   // 102400

__global__ __launch_bounds__(256, 2)
void attn_kernel(const float* __restrict__ Q, const float* __restrict__ K,
                 const float* __restrict__ V, const int* __restrict__ mask,
                 float* __restrict__ O)
{
    extern __shared__ float sm[];
    float (*Qs)[132] = (float(*)[132])(sm);
    float (*Ks)[68]  = (float(*)[68]) (sm + 64 * 132);
    float (*Vs)[68]  = (float(*)[68]) (sm + 64 * 132 + 64 * 68);
    float (*Ps)[132] = (float(*)[132])(sm + 64 * 132 + 2 * 64 * 68);
    __shared__ int msk[64];

    const int tid = threadIdx.x;
    const int tx  = tid & 15;
    const int ty  = tid >> 4;
    const int r0  = ty * 8;       // query rows   r0..r0+7
    const int c0  = tx * 4;       // key cols / dk cols c0..c0+3
    const int bh  = blockIdx.y;
    const int b   = bh >> 4;
    const int h   = bh & 15;
    const int q0  = blockIdx.x * 128;

    const float* Qg = Q + (size_t)b * SEQ * DIM + (size_t)h * DK;
    const float* Kg = K + (size_t)b * SEQ * DIM + (size_t)h * DK;
    const float* Vg = V + (size_t)b * SEQ * DIM + (size_t)h * DK;

    // Q tile 128x64, store transposed [dk][row]
    {
        const int lr = tid >> 4;
        const int lc = (tid & 15) * 4;
#pragma unroll
        for (int it = 0; it < 8; ++it) {
            const int r = lr + it * 16;
            float4 v = *(const float4*)&Qg[(size_t)(q0 + r) * DIM + lc];
            Qs[lc + 0][r] = v.x; Qs[lc + 1][r] = v.y;
            Qs[lc + 2][r] = v.z; Qs[lc + 3][r] = v.w;
        }
    }

    float m_i[8], l_i[8], Oacc[8][4];
#pragma unroll
    for (int i = 0; i < 8; ++i) {
        m_i[i] = -1e30f; l_i[i] = 0.f;
#pragma unroll
        for (int j = 0; j < 4; ++j) Oacc[i][j] = 0.f;
    }

    for (int kb = 0; kb < SEQ; kb += 64) {
        __syncthreads();   // protect Ks/Vs reuse + (iter0) Qs visibility
        {
            const int lr = tid >> 4;
            const int lc = (tid & 15) * 4;
#pragma unroll
            for (int it = 0; it < 4; ++it) {
                const int r = lr + it * 16;
                float4 kv = *(const float4*)&Kg[(size_t)(kb + r) * DIM + lc];
                Ks[lc + 0][r] = kv.x; Ks[lc + 1][r] = kv.y;
                Ks[lc + 2][r] = kv.z; Ks[lc + 3][r] = kv.w;
                float4 vv = *(const float4*)&Vg[(size_t)(kb + r) * DIM + lc];
                *(float4*)&Vs[r][lc] = vv;
            }
            if (tid < 64) msk[tid] = mask[b * SEQ + kb + tid];
        }
        __syncthreads();

        // S tile: acc[i][j] = sum_k Q[r0+i][k] * K[c0+j][k]   (pre-scaled Q)
        float acc[8][4];
#pragma unroll
        for (int i = 0; i < 8; ++i)
#pragma unroll
            for (int j = 0; j < 4; ++j) acc[i][j] = 0.f;

#pragma unroll 16
        for (int kk = 0; kk < 64; ++kk) {
            float4 qa = *(const float4*)&Qs[kk][r0];
            float4 qb = *(const float4*)&Qs[kk][r0 + 4];
            float4 kv = *(const float4*)&Ks[kk][c0];
            float qr[8] = {qa.x, qa.y, qa.z, qa.w, qb.x, qb.y, qb.z, qb.w};
            float kr[4] = {kv.x, kv.y, kv.z, kv.w};
#pragma unroll
            for (int i = 0; i < 8; ++i)
#pragma unroll
                for (int j = 0; j < 4; ++j)
                    acc[i][j] = fmaf(qr[i], kr[j], acc[i][j]);
        }

        // mask (score -> -1e9 where mask==0; matches reference exactly)
#pragma unroll
        for (int j = 0; j < 4; ++j) {
            if (msk[c0 + j] == 0) {
#pragma unroll
                for (int i = 0; i < 8; ++i) acc[i][j] = -1e9f;
            }
        }

        // online softmax update (row groups = 16 lanes sharing ty)
        float scl[8];
#pragma unroll
        for (int i = 0; i < 8; ++i) {
            float mt = fmaxf(fmaxf(acc[i][0], acc[i][1]), fmaxf(acc[i][2], acc[i][3]));
#pragma unroll
            for (int o = 8; o >= 1; o >>= 1)
                mt = fmaxf(mt, __shfl_xor_sync(0xffffffffu, mt, o));
            const float mnew = fmaxf(m_i[i], mt);
            scl[i] = __expf(m_i[i] - mnew);
            m_i[i] = mnew;
            float rs = 0.f;
#pragma unroll
            for (int j = 0; j < 4; ++j) {
                acc[i][j] = __expf(acc[i][j] - mnew);
                rs += acc[i][j];
            }
#pragma unroll
            for (int o = 8; o >= 1; o >>= 1)
                rs += __shfl_xor_sync(0xffffffffu, rs, o);
            l_i[i] = l_i[i] * scl[i] + rs;
#pragma unroll
            for (int j = 0; j < 4; ++j) Oacc[i][j] *= scl[i];
        }

        // write P transposed: Ps[key][row]
#pragma unroll
        for (int j = 0; j < 4; ++j) {
            *(float4*)&Ps[c0 + j][r0] =
                make_float4(acc[0][j], acc[1][j], acc[2][j], acc[3][j]);
            *(float4*)&Ps[c0 + j][r0 + 4] =
                make_float4(acc[4][j], acc[5][j], acc[6][j], acc[7][j]);
        }
        __syncthreads();

        // O += P @ V
#pragma unroll 16
        for (int j = 0; j < 64; ++j) {
            float4 pa = *(const float4*)&Ps[j][r0];
            float4 pb = *(const float4*)&Ps[j][r0 + 4];
            float4 vv = *(const float4*)&Vs[j][c0];
            float pr[8] = {pa.x, pa.y, pa.z, pa.w, pb.x, pb.y, pb.z, pb.w};
            float vr[4] = {vv.x, vv.y, vv.z, vv.w};
#pragma unroll
            for (int i = 0; i < 8; ++i)
#pragma unroll
                for (int jj = 0; jj < 4; ++jj)
                    Oacc[i][jj] = fmaf(pr[i], vr[jj], Oacc[i][jj]);
        }
    }

    float* Og = O + (size_t)b * SEQ * DIM + (size_t)h * DK;
#pragma unroll
    for (int i = 0; i < 8; ++i) {
        const float inv = 1.f / l_i[i];
        float4 o4 = make_float4(Oacc[i][0] * inv, Oacc[i][1] * inv,
                                Oacc[i][2] * inv, Oacc[i][3] * inv);
        *(float4*)&Og[(size_t)(q0 + r0 + i) * DIM + c0] = o4;
    }
}

// ---------------------------------------------------------------------------
// LayerNorm over last dim (1024). One block per row, 256 threads x float4.
// ---------------------------------------------------------------------------
__global__ __launch_bounds__(256)
void layernorm_kernel(const float* __restrict__ in, const float* __restrict__ g,
                      const float* __restrict__ b, float* __restrict__ out)
{
    const int row = blockIdx.x;
    const int tid = threadIdx.x;
    const float4 v = ((const float4*)(in + (size_t)row * DIM))[tid];
    float s  = v.x + v.y + v.z + v.w;
    float sq = fmaf(v.x, v.x, fmaf(v.y, v.y, fmaf(v.z, v.z, v.w * v.w)));

#pragma unroll
    for (int o = 16; o >= 1; o >>= 1) {
        s  += __shfl_xor_sync(0xffffffffu, s,  o);
        sq += __shfl_xor_sync(0xffffffffu, sq, o);
    }
    __shared__ float ss[8], ssq[8];
    const int warp = tid >> 5, lane = tid & 31;
    if (lane == 0) { ss[warp] = s; ssq[warp] = sq; }
    __syncthreads();
    if (warp == 0) {
        float a = (lane < 8) ? ss[lane]  : 0.f;
        float q = (lane < 8) ? ssq[lane] : 0.f;
#pragma unroll
        for (int o = 4; o >= 1; o >>= 1) {
            a += __shfl_xor_sync(0xffffffffu, a, o);
            q += __shfl_xor_sync(0xffffffffu, q, o);
        }
        if (lane == 0) { ss[0] = a; ssq[0] = q; }
    }
    __syncthreads();
    const float mu   = ss[0]  * (1.f / DIM);
    const float var  = ssq[0] * (1.f / DIM) - mu * mu;
    const float rstd = rsqrtf(var + 1e-5f);

    const float4 gg = ((const float4*)g)[tid];
    const float4 bb = ((const float4*)b)[tid];
    float4 o;
    o.x = (v.x - mu) * rstd * gg.x + bb.x;
    o.y = (v.y - mu) * rstd * gg.y + bb.y;
    o.z = (v.z - mu) * rstd * gg.z + bb.z;
    o.w = (v.w - mu) * rstd * gg.w + bb.w;
    ((float4*)(out + (size_t)row * DIM))[tid] = o;
}

// ---------------------------------------------------------------------------
static float* sym_addr(const void* s)
{
    void* p = nullptr;
    cudaGetSymbolAddress(&p, s);
    return (float*)p;
}

extern "C" void kernel_launch(void* const* d_in, const int* in_sizes, int n_in,
                              void* d_out, int out_size)
{
    const float* x     = (const float*)d_in[0];
    const int*   mask  = (const int*)  d_in[1];
    const float* Wq    = (const float*)d_in[2];
    const float* Wk    = (const float*)d_in[3];
    const float* Wv    = (const float*)d_in[4];
    const float* Wo    = (const float*)d_in[5];
    const float* W1    = (const float*)d_in[6];
    const float* b1    = (const float*)d_in[7];
    const float* W2    = (const float*)d_in[8];
    const float* b2    = (const float*)d_in[9];
    const float* ln1_g = (const float*)d_in[10];
    const float* ln1_b = (const float*)d_in[11];
    const float* ln2_g = (const float*)d_in[12];
    const float* ln2_b = (const float*)d_in[13];
    float* out = (float*)d_out;

    float* Qb  = sym_addr(g_Q);
    float* Kb  = sym_addr(g_K);
    float* Vb  = sym_addr(g_V);
    float* Cx  = sym_addr(g_ctx);
    float* T1  = sym_addr(g_t1);
    float* Hb  = sym_addr(g_h);
    float* Ff  = sym_addr(g_ff);

    static bool attr_set = false;
    if (!attr_set) {
        cudaFuncSetAttribute(attn_kernel,
                             cudaFuncAttributeMaxDynamicSharedMemorySize,
                             ATT_SMEM_BYTES);
        attr_set = true;
    }

    const dim3 blk(256);
    const dim3 gD  (DIM / 128, TOK / 128);   // (8, 64)
    const dim3 gDFF(DFF / 128, TOK / 128);   // (32, 64)

    // projections (1/sqrt(dk)=0.125 folded into Q)
    sgemm<false, false, false><<<gD, blk>>>(x, Wq, nullptr, nullptr, Qb, TOK, DIM, DIM, 0.125f);
    sgemm<false, false, false><<<gD, blk>>>(x, Wk, nullptr, nullptr, Kb, TOK, DIM, DIM, 1.0f);
    sgemm<false, false, false><<<gD, blk>>>(x, Wv, nullptr, nullptr, Vb, TOK, DIM, DIM, 1.0f);

    // attention
    attn_kernel<<<dim3(SEQ / 128, NB * NH), blk, ATT_SMEM_BYTES>>>(Qb, Kb, Vb, mask, Cx);

    // output projection + residual, LN1
    sgemm<false, false, true><<<gD, blk>>>(Cx, Wo, nullptr, x, T1, TOK, DIM, DIM, 1.0f);
    layernorm_kernel<<<TOK, blk>>>(T1, ln1_g, ln1_b, Hb);

    // FFN + residual, LN2
    sgemm<true, true,  false><<<gDFF, blk>>>(Hb, W1, b1, nullptr, Ff, TOK, DFF, DIM, 1.0f);
    sgemm<true, false, true ><<<gD,   blk>>>(Ff, W2, b2, Hb,      T1, TOK, DIM, DFF, 1.0f);
    layernorm_kernel<<<TOK, blk>>>(T1, ln2_g, ln2_b, out);
}

// round 10
// speedup vs baseline: 1.8299x; 1.8299x over previous
#include <cuda_runtime.h>
#include <cuda_bf16.h>
#include <cstdint>

// ---------------------------------------------------------------------------
// EncoderLayer: B=4 S=2048 D=1024 H=16 dk=64 Dff=4096, fp32 in/out.
// GEMMs: warp-level mma.sync bf16 (HMMA) with split-bf16 (hi/lo, 3 terms)
// error compensation. NOTE: tcgen05 is unavailable — harness PTX target is
// plain sm_103 (no 'a'); mma.sync/ldmatrix are portable sm_80+ features.
// Attention: fp32 SIMT (tensorize next round). LayerNorm: fp32.
// ---------------------------------------------------------------------------

constexpr int NB  = 4;
constexpr int SEQ = 2048;
constexpr int DIM = 1024;
constexpr int NH  = 16;
constexpr int DK  = 64;
constexpr int DFF = 4096;
constexpr int TOK = NB * SEQ;          // 8192

// scratch (device globals: allocation-free per harness rules)
__device__ float g_Q  [TOK * DIM];
__device__ float g_K  [TOK * DIM];
__device__ float g_V  [TOK * DIM];
__device__ float g_ctx[TOK * DIM];
__device__ float g_t1 [TOK * DIM];
__device__ float g_h  [TOK * DIM];
__device__ float g_ff [(size_t)TOK * DFF];
// pre-split weights, [N][K] layout, bf16 hi/lo.
constexpr size_t WOFF_Q  = 0;
constexpr size_t WOFF_K  = 1ull << 20;
constexpr size_t WOFF_V  = 2ull << 20;
constexpr size_t WOFF_O  = 3ull << 20;
constexpr size_t WOFF_W1 = 4ull << 20;
constexpr size_t WOFF_W2 = 8ull << 20;
__device__ __nv_bfloat16 g_wh[12ull << 20];
__device__ __nv_bfloat16 g_wl[12ull << 20];

// ===========================================================================
// helpers
// ===========================================================================
__device__ __forceinline__ uint32_t smem_u32(const void* p) {
    uint32_t a;
    asm("{ .reg .u64 t; cvta.to.shared.u64 t, %1; cvt.u32.u64 %0, t; }"
        : "=r"(a) : "l"(p));
    return a;
}

#define LDSM4(r, addr) \
    asm volatile("ldmatrix.sync.aligned.m8n8.x4.shared.b16 {%0,%1,%2,%3}, [%4];" \
        : "=r"((r)[0]), "=r"((r)[1]), "=r"((r)[2]), "=r"((r)[3]) : "r"(addr))

#define MMA16816(d, a, b) \
    asm volatile("mma.sync.aligned.m16n8k16.row.col.f32.bf16.bf16.f32 " \
        "{%0,%1,%2,%3}, {%4,%5,%6,%7}, {%8,%9}, {%0,%1,%2,%3};" \
        : "+f"((d)[0]), "+f"((d)[1]), "+f"((d)[2]), "+f"((d)[3]) \
        : "r"((a)[0]), "r"((a)[1]), "r"((a)[2]), "r"((a)[3]), \
          "r"((b)[0]), "r"((b)[1]))

__device__ __forceinline__ uint32_t bfpack(__nv_bfloat16 a, __nv_bfloat16 b) {
    __nv_bfloat162 t; t.x = a; t.y = b;
    return *reinterpret_cast<uint32_t*>(&t);
}
__device__ __forceinline__ void bsplit(float v, __nv_bfloat16& h, __nv_bfloat16& l) {
    h = __float2bfloat16(v);
    l = __float2bfloat16(v - __bfloat162float(h));
}

// ===========================================================================
// Weight pre-pass: W[K,N] fp32 -> hi/lo bf16 in [N,K] layout (transposed).
// ===========================================================================
__global__ __launch_bounds__(256)
void wsplit(const float* __restrict__ W, int K, int N,
            __nv_bfloat16* __restrict__ oh, __nv_bfloat16* __restrict__ ol)
{
    __shared__ float t[32][33];
    const int k0 = blockIdx.y * 32, n0 = blockIdx.x * 32;
    const int tx = threadIdx.x & 31, ty = threadIdx.x >> 5;
#pragma unroll
    for (int j = ty; j < 32; j += 8)
        t[j][tx] = W[(size_t)(k0 + j) * N + n0 + tx];
    __syncthreads();
#pragma unroll
    for (int j = ty; j < 32; j += 8) {
        float v = t[tx][j];                       // = W[k0+tx][n0+j]
        __nv_bfloat16 h, l; bsplit(v, h, l);
        oh[(size_t)(n0 + j) * K + k0 + tx] = h;
        ol[(size_t)(n0 + j) * K + k0 + tx] = l;
    }
}

// ===========================================================================
// HMMA GEMM: C[M,N] = epi(alpha * A[M,K] @ B[K,N]), B pre-split bf16 hi/lo
// in [N,K]. Block tile 128x64, BK=32, 256 thr, 8 warps (4M x 2N) of 32x32.
// Split-bf16: acc += Ah@Bh + Ah@Bl + Al@Bh. Double-buffered smem.
// smem stage (bf16, stride 40/row): Ah[128][40] Al[128][40] Bh[64][40] Bl[64][40]
//   = 30720 B; two stages = 61440 B dynamic.
// ===========================================================================
constexpr int HG_STAGE  = 30720;
constexpr int HG_SMEM   = 2 * HG_STAGE;
constexpr int OFF_AL    = 10240;
constexpr int OFF_BH    = 20480;
constexpr int OFF_BL    = 25600;

template<bool BIAS, bool RELU, bool RES>
__global__ __launch_bounds__(256)
void hgemm(const float* __restrict__ A,
           const __nv_bfloat16* __restrict__ Bhg,
           const __nv_bfloat16* __restrict__ Blg,
           const float* __restrict__ bias, const float* __restrict__ res,
           float* __restrict__ C, int N, int K, float alpha)
{
    extern __shared__ char smem[];
    const uint32_t sbase = smem_u32(smem);

    const int tid    = threadIdx.x;
    const int lane   = tid & 31;
    const int wid    = tid >> 5;
    const int warp_m = wid & 3;         // 4 warps in M
    const int warp_n = wid >> 2;        // 2 warps in N
    const int mbase  = warp_m * 32;
    const int nbase  = warp_n * 32;
    const int row0   = blockIdx.y * 128;
    const int col0   = blockIdx.x * 64;

    const int nk = K >> 5;              // BK=32

    float acc[2][4][4];
#pragma unroll
    for (int mt = 0; mt < 2; ++mt)
#pragma unroll
        for (int nt = 0; nt < 4; ++nt)
#pragma unroll
            for (int i = 0; i < 4; ++i) acc[mt][nt][i] = 0.f;

    // per-thread load indices
    const int ar = tid >> 1;                       // unused path removed
    (void)ar;

    float4 pa[4];
    uint2  pbh[2], pbl[2];

    const float* Ab = A + (size_t)row0 * K;

    // ---- prologue: load stage 0 into regs, store to buffer 0 ----
#pragma unroll
    for (int it = 0; it < 4; ++it) {
        int idx = it * 256 + tid, r = idx >> 3, c4 = idx & 7;
        pa[it] = *(const float4*)&Ab[(size_t)r * K + c4 * 4];
    }
#pragma unroll
    for (int it = 0; it < 2; ++it) {
        int idx = it * 256 + tid, r = idx >> 3, c4 = idx & 7;
        pbh[it] = *(const uint2*)&Bhg[(size_t)(col0 + r) * K + c4 * 4];
        pbl[it] = *(const uint2*)&Blg[(size_t)(col0 + r) * K + c4 * 4];
    }
    {
        char* st = smem;
#pragma unroll
        for (int it = 0; it < 4; ++it) {
            int idx = it * 256 + tid, r = idx >> 3, c4 = idx & 7;
            __nv_bfloat16 h0,h1,h2,h3,l0,l1,l2,l3;
            bsplit(pa[it].x,h0,l0); bsplit(pa[it].y,h1,l1);
            bsplit(pa[it].z,h2,l2); bsplit(pa[it].w,h3,l3);
            uint32_t off = (uint32_t)(r * 40 + c4 * 4) * 2;
            uint2 hp; hp.x = bfpack(h0,h1); hp.y = bfpack(h2,h3);
            uint2 lp; lp.x = bfpack(l0,l1); lp.y = bfpack(l2,l3);
            *(uint2*)(st + off)           = hp;
            *(uint2*)(st + OFF_AL + off)  = lp;
        }
#pragma unroll
        for (int it = 0; it < 2; ++it) {
            int idx = it * 256 + tid, r = idx >> 3, c4 = idx & 7;
            uint32_t off = (uint32_t)(r * 40 + c4 * 4) * 2;
            *(uint2*)(st + OFF_BH + off) = pbh[it];
            *(uint2*)(st + OFF_BL + off) = pbl[it];
        }
    }
    __syncthreads();

    for (int kb = 0; kb < nk; ++kb) {
        // prefetch next stage into regs (overlaps with compute below)
        if (kb + 1 < nk) {
            const float* Ap = Ab + ((kb + 1) << 5);
#pragma unroll
            for (int it = 0; it < 4; ++it) {
                int idx = it * 256 + tid, r = idx >> 3, c4 = idx & 7;
                pa[it] = *(const float4*)&Ap[(size_t)r * K + c4 * 4];
            }
            const size_t bofs = ((size_t)(kb + 1) << 5);
#pragma unroll
            for (int it = 0; it < 2; ++it) {
                int idx = it * 256 + tid, r = idx >> 3, c4 = idx & 7;
                pbh[it] = *(const uint2*)&Bhg[(size_t)(col0 + r) * K + bofs + c4 * 4];
                pbl[it] = *(const uint2*)&Blg[(size_t)(col0 + r) * K + bofs + c4 * 4];
            }
        }

        // ---- compute current stage ----
        const uint32_t sb = sbase + (uint32_t)(kb & 1) * HG_STAGE;
#pragma unroll
        for (int ks = 0; ks < 2; ++ks) {
            uint32_t ah[2][4], al[2][4], bh[4][2], bl[4][2];
#pragma unroll
            for (int mt = 0; mt < 2; ++mt) {
                int row = mbase + mt * 16 + (lane & 15);
                int col = ks * 16 + ((lane >> 4) << 3);
                uint32_t ad = sb + (uint32_t)(row * 40 + col) * 2;
                LDSM4(ah[mt], ad);
                LDSM4(al[mt], ad + OFF_AL);
            }
#pragma unroll
            for (int np = 0; np < 2; ++np) {
                int grp  = lane >> 3;
                int nrow = nbase + np * 16 + ((grp >> 1) << 3) + (lane & 7);
                int kcol = ks * 16 + ((grp & 1) << 3);
                uint32_t bd = sb + OFF_BH + (uint32_t)(nrow * 40 + kcol) * 2;
                uint32_t q[4];
                LDSM4(q, bd);
                bh[np*2][0] = q[0]; bh[np*2][1] = q[1];
                bh[np*2+1][0] = q[2]; bh[np*2+1][1] = q[3];
                LDSM4(q, bd + (OFF_BL - OFF_BH));
                bl[np*2][0] = q[0]; bl[np*2][1] = q[1];
                bl[np*2+1][0] = q[2]; bl[np*2+1][1] = q[3];
            }
#pragma unroll
            for (int mt = 0; mt < 2; ++mt)
#pragma unroll
                for (int nt = 0; nt < 4; ++nt) {
                    MMA16816(acc[mt][nt], ah[mt], bh[nt]);
                    MMA16816(acc[mt][nt], ah[mt], bl[nt]);
                    MMA16816(acc[mt][nt], al[mt], bh[nt]);
                }
        }

        // ---- store next stage (waits on prefetch loads via scoreboard) ----
        if (kb + 1 < nk) {
            char* st = smem + ((kb + 1) & 1) * HG_STAGE;
#pragma unroll
            for (int it = 0; it < 4; ++it) {
                int idx = it * 256 + tid, r = idx >> 3, c4 = idx & 7;
                __nv_bfloat16 h0,h1,h2,h3,l0,l1,l2,l3;
                bsplit(pa[it].x,h0,l0); bsplit(pa[it].y,h1,l1);
                bsplit(pa[it].z,h2,l2); bsplit(pa[it].w,h3,l3);
                uint32_t off = (uint32_t)(r * 40 + c4 * 4) * 2;
                uint2 hp; hp.x = bfpack(h0,h1); hp.y = bfpack(h2,h3);
                uint2 lp; lp.x = bfpack(l0,l1); lp.y = bfpack(l2,l3);
                *(uint2*)(st + off)          = hp;
                *(uint2*)(st + OFF_AL + off) = lp;
            }
#pragma unroll
            for (int it = 0; it < 2; ++it) {
                int idx = it * 256 + tid, r = idx >> 3, c4 = idx & 7;
                uint32_t off = (uint32_t)(r * 40 + c4 * 4) * 2;
                *(uint2*)(st + OFF_BH + off) = pbh[it];
                *(uint2*)(st + OFF_BL + off) = pbl[it];
            }
        }
        __syncthreads();
    }

    // ---- epilogue: fragment -> global (quad-contiguous float2 stores) ----
    const int quad  = lane >> 2;
    const int qlane = lane & 3;
#pragma unroll
    for (int mt = 0; mt < 2; ++mt) {
#pragma unroll
        for (int nt = 0; nt < 4; ++nt) {
            const int cg = col0 + nbase + nt * 8 + (qlane << 1);
#pragma unroll
            for (int h = 0; h < 2; ++h) {
                const int rg = row0 + mbase + mt * 16 + quad + h * 8;
                float2 v;
                v.x = acc[mt][nt][h * 2 + 0] * alpha;
                v.y = acc[mt][nt][h * 2 + 1] * alpha;
                if (BIAS) {
                    float2 bb = *(const float2*)&bias[cg];
                    v.x += bb.x; v.y += bb.y;
                }
                if (RES) {
                    float2 rr = *(const float2*)&res[(size_t)rg * N + cg];
                    v.x += rr.x; v.y += rr.y;
                }
                if (RELU) { v.x = fmaxf(v.x, 0.f); v.y = fmaxf(v.y, 0.f); }
                *(float2*)&C[(size_t)rg * N + cg] = v;
            }
        }
    }
}

// ===========================================================================
// Flash attention, fp32 SIMT (unchanged from R5 passing version).
// ===========================================================================
constexpr int ATT_SMEM_FLOATS = 64 * 132 + 64 * 68 + 64 * 68 + 64 * 132;
constexpr int ATT_SMEM_BYTES  = ATT_SMEM_FLOATS * 4;

__global__ __launch_bounds__(256, 2)
void attn_kernel(const float* __restrict__ Q, const float* __restrict__ K,
                 const float* __restrict__ V, const int* __restrict__ mask,
                 float* __restrict__ O)
{
    extern __shared__ float sm[];
    float (*Qs)[132] = (float(*)[132])(sm);
    float (*Ks)[68]  = (float(*)[68]) (sm + 64 * 132);
    float (*Vs)[68]  = (float(*)[68]) (sm + 64 * 132 + 64 * 68);
    float (*Ps)[132] = (float(*)[132])(sm + 64 * 132 + 2 * 64 * 68);
    __shared__ int msk[64];

    const int tid = threadIdx.x;
    const int tx  = tid & 15;
    const int ty  = tid >> 4;
    const int r0  = ty * 8;
    const int c0  = tx * 4;
    const int bh  = blockIdx.y;
    const int b   = bh >> 4;
    const int h   = bh & 15;
    const int q0  = blockIdx.x * 128;

    const float* Qg = Q + (size_t)b * SEQ * DIM + (size_t)h * DK;
    const float* Kg = K + (size_t)b * SEQ * DIM + (size_t)h * DK;
    const float* Vg = V + (size_t)b * SEQ * DIM + (size_t)h * DK;

    {
        const int lr = tid >> 4;
        const int lc = (tid & 15) * 4;
#pragma unroll
        for (int it = 0; it < 8; ++it) {
            const int r = lr + it * 16;
            float4 v = *(const float4*)&Qg[(size_t)(q0 + r) * DIM + lc];
            Qs[lc + 0][r] = v.x; Qs[lc + 1][r] = v.y;
            Qs[lc + 2][r] = v.z; Qs[lc + 3][r] = v.w;
        }
    }

    float m_i[8], l_i[8], Oacc[8][4];
#pragma unroll
    for (int i = 0; i < 8; ++i) {
        m_i[i] = -1e30f; l_i[i] = 0.f;
#pragma unroll
        for (int j = 0; j < 4; ++j) Oacc[i][j] = 0.f;
    }

    for (int kb = 0; kb < SEQ; kb += 64) {
        __syncthreads();
        {
            const int lr = tid >> 4;
            const int lc = (tid & 15) * 4;
#pragma unroll
            for (int it = 0; it < 4; ++it) {
                const int r = lr + it * 16;
                float4 kv = *(const float4*)&Kg[(size_t)(kb + r) * DIM + lc];
                Ks[lc + 0][r] = kv.x; Ks[lc + 1][r] = kv.y;
                Ks[lc + 2][r] = kv.z; Ks[lc + 3][r] = kv.w;
                float4 vv = *(const float4*)&Vg[(size_t)(kb + r) * DIM + lc];
                *(float4*)&Vs[r][lc] = vv;
            }
            if (tid < 64) msk[tid] = mask[b * SEQ + kb + tid];
        }
        __syncthreads();

        float acc[8][4];
#pragma unroll
        for (int i = 0; i < 8; ++i)
#pragma unroll
            for (int j = 0; j < 4; ++j) acc[i][j] = 0.f;

#pragma unroll 16
        for (int kk = 0; kk < 64; ++kk) {
            float4 qa = *(const float4*)&Qs[kk][r0];
            float4 qb = *(const float4*)&Qs[kk][r0 + 4];
            float4 kv = *(const float4*)&Ks[kk][c0];
            float qr[8] = {qa.x, qa.y, qa.z, qa.w, qb.x, qb.y, qb.z, qb.w};
            float kr[4] = {kv.x, kv.y, kv.z, kv.w};
#pragma unroll
            for (int i = 0; i < 8; ++i)
#pragma unroll
                for (int j = 0; j < 4; ++j)
                    acc[i][j] = fmaf(qr[i], kr[j], acc[i][j]);
        }

#pragma unroll
        for (int j = 0; j < 4; ++j) {
            if (msk[c0 + j] == 0) {
#pragma unroll
                for (int i = 0; i < 8; ++i) acc[i][j] = -1e9f;
            }
        }

        float scl[8];
#pragma unroll
        for (int i = 0; i < 8; ++i) {
            float mt = fmaxf(fmaxf(acc[i][0], acc[i][1]), fmaxf(acc[i][2], acc[i][3]));
#pragma unroll
            for (int o = 8; o >= 1; o >>= 1)
                mt = fmaxf(mt, __shfl_xor_sync(0xffffffffu, mt, o));
            const float mnew = fmaxf(m_i[i], mt);
            scl[i] = __expf(m_i[i] - mnew);
            m_i[i] = mnew;
            float rs = 0.f;
#pragma unroll
            for (int j = 0; j < 4; ++j) {
                acc[i][j] = __expf(acc[i][j] - mnew);
                rs += acc[i][j];
            }
#pragma unroll
            for (int o = 8; o >= 1; o >>= 1)
                rs += __shfl_xor_sync(0xffffffffu, rs, o);
            l_i[i] = l_i[i] * scl[i] + rs;
#pragma unroll
            for (int j = 0; j < 4; ++j) Oacc[i][j] *= scl[i];
        }

#pragma unroll
        for (int j = 0; j < 4; ++j) {
            *(float4*)&Ps[c0 + j][r0] =
                make_float4(acc[0][j], acc[1][j], acc[2][j], acc[3][j]);
            *(float4*)&Ps[c0 + j][r0 + 4] =
                make_float4(acc[4][j], acc[5][j], acc[6][j], acc[7][j]);
        }
        __syncthreads();

#pragma unroll 16
        for (int j = 0; j < 64; ++j) {
            float4 pa = *(const float4*)&Ps[j][r0];
            float4 pb = *(const float4*)&Ps[j][r0 + 4];
            float4 vv = *(const float4*)&Vs[j][c0];
            float pr[8] = {pa.x, pa.y, pa.z, pa.w, pb.x, pb.y, pb.z, pb.w};
            float vr[4] = {vv.x, vv.y, vv.z, vv.w};
#pragma unroll
            for (int i = 0; i < 8; ++i)
#pragma unroll
                for (int jj = 0; jj < 4; ++jj)
                    Oacc[i][jj] = fmaf(pr[i], vr[jj], Oacc[i][jj]);
        }
    }

    float* Og = O + (size_t)b * SEQ * DIM + (size_t)h * DK;
#pragma unroll
    for (int i = 0; i < 8; ++i) {
        const float inv = 1.f / l_i[i];
        float4 o4 = make_float4(Oacc[i][0] * inv, Oacc[i][1] * inv,
                                Oacc[i][2] * inv, Oacc[i][3] * inv);
        *(float4*)&Og[(size_t)(q0 + r0 + i) * DIM + c0] = o4;
    }
}

// ===========================================================================
// LayerNorm over last dim (1024). One block per row, 256 threads x float4.
// ===========================================================================
__global__ __launch_bounds__(256)
void layernorm_kernel(const float* __restrict__ in, const float* __restrict__ g,
                      const float* __restrict__ b, float* __restrict__ out)
{
    const int row = blockIdx.x;
    const int tid = threadIdx.x;
    const float4 v = ((const float4*)(in + (size_t)row * DIM))[tid];
    float s  = v.x + v.y + v.z + v.w;
    float sq = fmaf(v.x, v.x, fmaf(v.y, v.y, fmaf(v.z, v.z, v.w * v.w)));

#pragma unroll
    for (int o = 16; o >= 1; o >>= 1) {
        s  += __shfl_xor_sync(0xffffffffu, s,  o);
        sq += __shfl_xor_sync(0xffffffffu, sq, o);
    }
    __shared__ float ss[8], ssq[8];
    const int warp = tid >> 5, lane = tid & 31;
    if (lane == 0) { ss[warp] = s; ssq[warp] = sq; }
    __syncthreads();
    if (warp == 0) {
        float a = (lane < 8) ? ss[lane]  : 0.f;
        float q = (lane < 8) ? ssq[lane] : 0.f;
#pragma unroll
        for (int o = 4; o >= 1; o >>= 1) {
            a += __shfl_xor_sync(0xffffffffu, a, o);
            q += __shfl_xor_sync(0xffffffffu, q, o);
        }
        if (lane == 0) { ss[0] = a; ssq[0] = q; }
    }
    __syncthreads();
    const float mu   = ss[0]  * (1.f / DIM);
    const float var  = ssq[0] * (1.f / DIM) - mu * mu;
    const float rstd = rsqrtf(var + 1e-5f);

    const float4 gg = ((const float4*)g)[tid];
    const float4 bb = ((const float4*)b)[tid];
    float4 o;
    o.x = (v.x - mu) * rstd * gg.x + bb.x;
    o.y = (v.y - mu) * rstd * gg.y + bb.y;
    o.z = (v.z - mu) * rstd * gg.z + bb.z;
    o.w = (v.w - mu) * rstd * gg.w + bb.w;
    ((float4*)(out + (size_t)row * DIM))[tid] = o;
}

// ---------------------------------------------------------------------------
static void* sym_addr(const void* s)
{
    void* p = nullptr;
    cudaGetSymbolAddress(&p, s);
    return p;
}

extern "C" void kernel_launch(void* const* d_in, const int* in_sizes, int n_in,
                              void* d_out, int out_size)
{
    const float* x     = (const float*)d_in[0];
    const int*   mask  = (const int*)  d_in[1];
    const float* Wq    = (const float*)d_in[2];
    const float* Wk    = (const float*)d_in[3];
    const float* Wv    = (const float*)d_in[4];
    const float* Wo    = (const float*)d_in[5];
    const float* W1    = (const float*)d_in[6];
    const float* b1    = (const float*)d_in[7];
    const float* W2    = (const float*)d_in[8];
    const float* b2    = (const float*)d_in[9];
    const float* ln1_g = (const float*)d_in[10];
    const float* ln1_b = (const float*)d_in[11];
    const float* ln2_g = (const float*)d_in[12];
    const float* ln2_b = (const float*)d_in[13];
    float* out = (float*)d_out;

    float* Qb  = (float*)sym_addr(g_Q);
    float* Kb  = (float*)sym_addr(g_K);
    float* Vb  = (float*)sym_addr(g_V);
    float* Cx  = (float*)sym_addr(g_ctx);
    float* T1  = (float*)sym_addr(g_t1);
    float* Hb  = (float*)sym_addr(g_h);
    float* Ff  = (float*)sym_addr(g_ff);
    __nv_bfloat16* wh = (__nv_bfloat16*)sym_addr(g_wh);
    __nv_bfloat16* wl = (__nv_bfloat16*)sym_addr(g_wl);

    static bool attr_set = false;
    if (!attr_set) {
        cudaFuncSetAttribute(attn_kernel,
            cudaFuncAttributeMaxDynamicSharedMemorySize, ATT_SMEM_BYTES);
        cudaFuncSetAttribute(hgemm<false, false, false>,
            cudaFuncAttributeMaxDynamicSharedMemorySize, HG_SMEM);
        cudaFuncSetAttribute(hgemm<false, false, true>,
            cudaFuncAttributeMaxDynamicSharedMemorySize, HG_SMEM);
        cudaFuncSetAttribute(hgemm<true, true, false>,
            cudaFuncAttributeMaxDynamicSharedMemorySize, HG_SMEM);
        cudaFuncSetAttribute(hgemm<true, false, true>,
            cudaFuncAttributeMaxDynamicSharedMemorySize, HG_SMEM);
        attr_set = true;
    }

    const dim3 blk(256);

    // ---- weight pre-split ----
    wsplit<<<dim3(DIM / 32, DIM / 32), blk>>>(Wq, DIM, DIM, wh + WOFF_Q, wl + WOFF_Q);
    wsplit<<<dim3(DIM / 32, DIM / 32), blk>>>(Wk, DIM, DIM, wh + WOFF_K, wl + WOFF_K);
    wsplit<<<dim3(DIM / 32, DIM / 32), blk>>>(Wv, DIM, DIM, wh + WOFF_V, wl + WOFF_V);
    wsplit<<<dim3(DIM / 32, DIM / 32), blk>>>(Wo, DIM, DIM, wh + WOFF_O, wl + WOFF_O);
    wsplit<<<dim3(DFF / 32, DIM / 32), blk>>>(W1, DIM, DFF, wh + WOFF_W1, wl + WOFF_W1);
    wsplit<<<dim3(DIM / 32, DFF / 32), blk>>>(W2, DFF, DIM, wh + WOFF_W2, wl + WOFF_W2);

    const dim3 gD  (DIM / 64, TOK / 128);    // (16, 64)
    const dim3 gDFF(DFF / 64, TOK / 128);    // (64, 64)

    // projections (1/sqrt(dk)=0.125 folded into Q via alpha)
    hgemm<false, false, false><<<gD, blk, HG_SMEM>>>(
        x, wh + WOFF_Q, wl + WOFF_Q, nullptr, nullptr, Qb, DIM, DIM, 0.125f);
    hgemm<false, false, false><<<gD, blk, HG_SMEM>>>(
        x, wh + WOFF_K, wl + WOFF_K, nullptr, nullptr, Kb, DIM, DIM, 1.0f);
    hgemm<false, false, false><<<gD, blk, HG_SMEM>>>(
        x, wh + WOFF_V, wl + WOFF_V, nullptr, nullptr, Vb, DIM, DIM, 1.0f);

    // attention
    attn_kernel<<<dim3(SEQ / 128, NB * NH), blk, ATT_SMEM_BYTES>>>(Qb, Kb, Vb, mask, Cx);

    // output projection + residual, LN1
    hgemm<false, false, true><<<gD, blk, HG_SMEM>>>(
        Cx, wh + WOFF_O, wl + WOFF_O, nullptr, x, T1, DIM, DIM, 1.0f);
    layernorm_kernel<<<TOK, blk>>>(T1, ln1_g, ln1_b, Hb);

    // FFN + residual, LN2
    hgemm<true, true, false><<<gDFF, blk, HG_SMEM>>>(
        Hb, wh + WOFF_W1, wl + WOFF_W1, b1, nullptr, Ff, DFF, DIM, 1.0f);
    hgemm<true, false, true><<<gD, blk, HG_SMEM>>>(
        Ff, wh + WOFF_W2, wl + WOFF_W2, b2, Hb, T1, DIM, DFF, 1.0f);
    layernorm_kernel<<<TOK, blk>>>(T1, ln2_g, ln2_b, out);
}

// round 14
// speedup vs baseline: 2.4291x; 1.3275x over previous
#include <cuda_runtime.h>
#include <cuda_bf16.h>
#include <cstdint>

// ---------------------------------------------------------------------------
// EncoderLayer: B=4 S=2048 D=1024 H=16 dk=64 Dff=4096, fp32 in/out.
// GEMMs + attention on mma.sync bf16 (HMMA) with split-bf16 error compensation.
// QKV projections emit split-bf16 hi/lo directly for the attention kernel.
// Softmax exp via FMA-pipe polynomial (avoids 1.9ms MUFU floor).
// ---------------------------------------------------------------------------

constexpr int NB  = 4;
constexpr int SEQ = 2048;
constexpr int DIM = 1024;
constexpr int NH  = 16;
constexpr int DK  = 64;
constexpr int DFF = 4096;
constexpr int TOK = NB * SEQ;          // 8192

// scratch (device globals: allocation-free per harness rules)
__device__ float g_ctx[TOK * DIM];
__device__ float g_t1 [TOK * DIM];
__device__ float g_h  [TOK * DIM];
__device__ float g_ff [(size_t)TOK * DFF];
__device__ __nv_bfloat16 g_Qh[TOK * DIM], g_Ql[TOK * DIM];
__device__ __nv_bfloat16 g_Kh[TOK * DIM], g_Kl[TOK * DIM];
__device__ __nv_bfloat16 g_Vh[TOK * DIM], g_Vl[TOK * DIM];
// pre-split weights, [N][K] layout, bf16 hi/lo.
constexpr size_t WOFF_Q  = 0;
constexpr size_t WOFF_K  = 1ull << 20;
constexpr size_t WOFF_V  = 2ull << 20;
constexpr size_t WOFF_O  = 3ull << 20;
constexpr size_t WOFF_W1 = 4ull << 20;
constexpr size_t WOFF_W2 = 8ull << 20;
__device__ __nv_bfloat16 g_wh[12ull << 20];
__device__ __nv_bfloat16 g_wl[12ull << 20];

// ===========================================================================
// helpers
// ===========================================================================
__device__ __forceinline__ uint32_t smem_u32(const void* p) {
    uint32_t a;
    asm("{ .reg .u64 t; cvta.to.shared.u64 t, %1; cvt.u32.u64 %0, t; }"
        : "=r"(a) : "l"(p));
    return a;
}

#define LDSM4(r, addr) \
    asm volatile("ldmatrix.sync.aligned.m8n8.x4.shared.b16 {%0,%1,%2,%3}, [%4];" \
        : "=r"((r)[0]), "=r"((r)[1]), "=r"((r)[2]), "=r"((r)[3]) : "r"(addr))

#define MMA16816(d, a, b) \
    asm volatile("mma.sync.aligned.m16n8k16.row.col.f32.bf16.bf16.f32 " \
        "{%0,%1,%2,%3}, {%4,%5,%6,%7}, {%8,%9}, {%0,%1,%2,%3};" \
        : "+f"((d)[0]), "+f"((d)[1]), "+f"((d)[2]), "+f"((d)[3]) \
        : "r"((a)[0]), "r"((a)[1]), "r"((a)[2]), "r"((a)[3]), \
          "r"((b)[0]), "r"((b)[1]))

__device__ __forceinline__ uint32_t bfpack(__nv_bfloat16 a, __nv_bfloat16 b) {
    __nv_bfloat162 t; t.x = a; t.y = b;
    return *reinterpret_cast<uint32_t*>(&t);
}
__device__ __forceinline__ uint32_t fpack2(float a, float b) {
    return bfpack(__float2bfloat16(a), __float2bfloat16(b));
}
__device__ __forceinline__ void bsplit(float v, __nv_bfloat16& h, __nv_bfloat16& l) {
    h = __float2bfloat16(v);
    l = __float2bfloat16(v - __bfloat162float(h));
}

// fast exp on the FMA pipe: exp(x) = 2^(x*log2e), range-reduced, deg-5 poly.
__device__ __forceinline__ float fexp(float x) {
    x = fmaxf(x, -87.f);
    float t = fmaf(x, 1.4426950408889634f, 12582912.f);   // magic = 1.5*2^23
    int   n = __float_as_int(t) - 0x4B400000;
    float f = fmaf(x, 1.4426950408889634f, -(t - 12582912.f));
    float p =             1.3333558146e-3f;
    p = fmaf(p, f, 9.6181291076e-3f);
    p = fmaf(p, f, 5.5504108664e-2f);
    p = fmaf(p, f, 2.4022650696e-1f);
    p = fmaf(p, f, 6.9314718056e-1f);
    p = fmaf(p, f, 1.0f);
    return __int_as_float(__float_as_int(p) + (n << 23));
}

// ===========================================================================
// Weight pre-pass: W[K,N] fp32 -> hi/lo bf16 in [N,K] layout (transposed).
// ===========================================================================
__global__ __launch_bounds__(256)
void wsplit(const float* __restrict__ W, int K, int N,
            __nv_bfloat16* __restrict__ oh, __nv_bfloat16* __restrict__ ol)
{
    __shared__ float t[32][33];
    const int k0 = blockIdx.y * 32, n0 = blockIdx.x * 32;
    const int tx = threadIdx.x & 31, ty = threadIdx.x >> 5;
#pragma unroll
    for (int j = ty; j < 32; j += 8)
        t[j][tx] = W[(size_t)(k0 + j) * N + n0 + tx];
    __syncthreads();
#pragma unroll
    for (int j = ty; j < 32; j += 8) {
        float v = t[tx][j];
        __nv_bfloat16 h, l; bsplit(v, h, l);
        oh[(size_t)(n0 + j) * K + k0 + tx] = h;
        ol[(size_t)(n0 + j) * K + k0 + tx] = l;
    }
}

// ===========================================================================
// HMMA GEMM (as R10, plus SPLITOUT epilogue writing bf16 hi/lo).
// ===========================================================================
constexpr int HG_STAGE  = 30720;
constexpr int HG_SMEM   = 2 * HG_STAGE;
constexpr int OFF_AL    = 10240;
constexpr int OFF_BH    = 20480;
constexpr int OFF_BL    = 25600;

template<bool BIAS, bool RELU, bool RES, bool SPLITOUT>
__global__ __launch_bounds__(256)
void hgemm(const float* __restrict__ A,
           const __nv_bfloat16* __restrict__ Bhg,
           const __nv_bfloat16* __restrict__ Blg,
           const float* __restrict__ bias, const float* __restrict__ res,
           float* __restrict__ C,
           __nv_bfloat16* __restrict__ Ch, __nv_bfloat16* __restrict__ Cl,
           int N, int K, float alpha)
{
    extern __shared__ char smem[];
    const uint32_t sbase = smem_u32(smem);

    const int tid    = threadIdx.x;
    const int lane   = tid & 31;
    const int wid    = tid >> 5;
    const int warp_m = wid & 3;
    const int warp_n = wid >> 2;
    const int mbase  = warp_m * 32;
    const int nbase  = warp_n * 32;
    const int row0   = blockIdx.y * 128;
    const int col0   = blockIdx.x * 64;

    const int nk = K >> 5;

    float acc[2][4][4];
#pragma unroll
    for (int mt = 0; mt < 2; ++mt)
#pragma unroll
        for (int nt = 0; nt < 4; ++nt)
#pragma unroll
            for (int i = 0; i < 4; ++i) acc[mt][nt][i] = 0.f;

    float4 pa[4];
    uint2  pbh[2], pbl[2];
    const float* Ab = A + (size_t)row0 * K;

#pragma unroll
    for (int it = 0; it < 4; ++it) {
        int idx = it * 256 + tid, r = idx >> 3, c4 = idx & 7;
        pa[it] = *(const float4*)&Ab[(size_t)r * K + c4 * 4];
    }
#pragma unroll
    for (int it = 0; it < 2; ++it) {
        int idx = it * 256 + tid, r = idx >> 3, c4 = idx & 7;
        pbh[it] = *(const uint2*)&Bhg[(size_t)(col0 + r) * K + c4 * 4];
        pbl[it] = *(const uint2*)&Blg[(size_t)(col0 + r) * K + c4 * 4];
    }
    {
        char* st = smem;
#pragma unroll
        for (int it = 0; it < 4; ++it) {
            int idx = it * 256 + tid, r = idx >> 3, c4 = idx & 7;
            __nv_bfloat16 h0,h1,h2,h3,l0,l1,l2,l3;
            bsplit(pa[it].x,h0,l0); bsplit(pa[it].y,h1,l1);
            bsplit(pa[it].z,h2,l2); bsplit(pa[it].w,h3,l3);
            uint32_t off = (uint32_t)(r * 40 + c4 * 4) * 2;
            uint2 hp; hp.x = bfpack(h0,h1); hp.y = bfpack(h2,h3);
            uint2 lp; lp.x = bfpack(l0,l1); lp.y = bfpack(l2,l3);
            *(uint2*)(st + off)           = hp;
            *(uint2*)(st + OFF_AL + off)  = lp;
        }
#pragma unroll
        for (int it = 0; it < 2; ++it) {
            int idx = it * 256 + tid, r = idx >> 3, c4 = idx & 7;
            uint32_t off = (uint32_t)(r * 40 + c4 * 4) * 2;
            *(uint2*)(st + OFF_BH + off) = pbh[it];
            *(uint2*)(st + OFF_BL + off) = pbl[it];
        }
    }
    __syncthreads();

    for (int kb = 0; kb < nk; ++kb) {
        if (kb + 1 < nk) {
            const float* Ap = Ab + ((kb + 1) << 5);
#pragma unroll
            for (int it = 0; it < 4; ++it) {
                int idx = it * 256 + tid, r = idx >> 3, c4 = idx & 7;
                pa[it] = *(const float4*)&Ap[(size_t)r * K + c4 * 4];
            }
            const size_t bofs = ((size_t)(kb + 1) << 5);
#pragma unroll
            for (int it = 0; it < 2; ++it) {
                int idx = it * 256 + tid, r = idx >> 3, c4 = idx & 7;
                pbh[it] = *(const uint2*)&Bhg[(size_t)(col0 + r) * K + bofs + c4 * 4];
                pbl[it] = *(const uint2*)&Blg[(size_t)(col0 + r) * K + bofs + c4 * 4];
            }
        }

        const uint32_t sb = sbase + (uint32_t)(kb & 1) * HG_STAGE;
#pragma unroll
        for (int ks = 0; ks < 2; ++ks) {
            uint32_t ah[2][4], al[2][4], bh[4][2], bl[4][2];
#pragma unroll
            for (int mt = 0; mt < 2; ++mt) {
                int row = mbase + mt * 16 + (lane & 15);
                int col = ks * 16 + ((lane >> 4) << 3);
                uint32_t ad = sb + (uint32_t)(row * 40 + col) * 2;
                LDSM4(ah[mt], ad);
                LDSM4(al[mt], ad + OFF_AL);
            }
#pragma unroll
            for (int np = 0; np < 2; ++np) {
                int grp  = lane >> 3;
                int nrow = nbase + np * 16 + ((grp >> 1) << 3) + (lane & 7);
                int kcol = ks * 16 + ((grp & 1) << 3);
                uint32_t bd = sb + OFF_BH + (uint32_t)(nrow * 40 + kcol) * 2;
                uint32_t q[4];
                LDSM4(q, bd);
                bh[np*2][0] = q[0]; bh[np*2][1] = q[1];
                bh[np*2+1][0] = q[2]; bh[np*2+1][1] = q[3];
                LDSM4(q, bd + (OFF_BL - OFF_BH));
                bl[np*2][0] = q[0]; bl[np*2][1] = q[1];
                bl[np*2+1][0] = q[2]; bl[np*2+1][1] = q[3];
            }
#pragma unroll
            for (int mt = 0; mt < 2; ++mt)
#pragma unroll
                for (int nt = 0; nt < 4; ++nt) {
                    MMA16816(acc[mt][nt], ah[mt], bh[nt]);
                    MMA16816(acc[mt][nt], ah[mt], bl[nt]);
                    MMA16816(acc[mt][nt], al[mt], bh[nt]);
                }
        }

        if (kb + 1 < nk) {
            char* st = smem + ((kb + 1) & 1) * HG_STAGE;
#pragma unroll
            for (int it = 0; it < 4; ++it) {
                int idx = it * 256 + tid, r = idx >> 3, c4 = idx & 7;
                __nv_bfloat16 h0,h1,h2,h3,l0,l1,l2,l3;
                bsplit(pa[it].x,h0,l0); bsplit(pa[it].y,h1,l1);
                bsplit(pa[it].z,h2,l2); bsplit(pa[it].w,h3,l3);
                uint32_t off = (uint32_t)(r * 40 + c4 * 4) * 2;
                uint2 hp; hp.x = bfpack(h0,h1); hp.y = bfpack(h2,h3);
                uint2 lp; lp.x = bfpack(l0,l1); lp.y = bfpack(l2,l3);
                *(uint2*)(st + off)          = hp;
                *(uint2*)(st + OFF_AL + off) = lp;
            }
#pragma unroll
            for (int it = 0; it < 2; ++it) {
                int idx = it * 256 + tid, r = idx >> 3, c4 = idx & 7;
                uint32_t off = (uint32_t)(r * 40 + c4 * 4) * 2;
                *(uint2*)(st + OFF_BH + off) = pbh[it];
                *(uint2*)(st + OFF_BL + off) = pbl[it];
            }
        }
        __syncthreads();
    }

    const int quad  = lane >> 2;
    const int qlane = lane & 3;
#pragma unroll
    for (int mt = 0; mt < 2; ++mt) {
#pragma unroll
        for (int nt = 0; nt < 4; ++nt) {
            const int cg = col0 + nbase + nt * 8 + (qlane << 1);
#pragma unroll
            for (int h = 0; h < 2; ++h) {
                const int rg = row0 + mbase + mt * 16 + quad + h * 8;
                float2 v;
                v.x = acc[mt][nt][h * 2 + 0] * alpha;
                v.y = acc[mt][nt][h * 2 + 1] * alpha;
                if (BIAS) {
                    float2 bb = *(const float2*)&bias[cg];
                    v.x += bb.x; v.y += bb.y;
                }
                if (RES) {
                    float2 rr = *(const float2*)&res[(size_t)rg * N + cg];
                    v.x += rr.x; v.y += rr.y;
                }
                if (RELU) { v.x = fmaxf(v.x, 0.f); v.y = fmaxf(v.y, 0.f); }
                if (SPLITOUT) {
                    __nv_bfloat16 hx, lx, hy, ly;
                    bsplit(v.x, hx, lx); bsplit(v.y, hy, ly);
                    *(uint32_t*)&Ch[(size_t)rg * N + cg] = bfpack(hx, hy);
                    *(uint32_t*)&Cl[(size_t)rg * N + cg] = bfpack(lx, ly);
                } else {
                    *(float2*)&C[(size_t)rg * N + cg] = v;
                }
            }
        }
    }
}

// ===========================================================================
// Tensorized flash attention.
// Grid (SEQ/128, NB*NH), 256 thr = 8 warps x 16 query rows. Key tile = 64.
// QK^T: 3-term split-bf16; PV: plain-bf16 P x (Vh + Vl).
// smem bf16 stride 72/row (144B: conflict-free ldmatrix).
// ===========================================================================
constexpr int AT_S     = 72;                    // row stride in bf16
constexpr int QL_OFF   = 128 * AT_S;            // elem offsets
constexpr int KH_OFF   = 2 * QL_OFF;
constexpr int KL_OFF   = KH_OFF + 64 * AT_S;
constexpr int VH_OFF   = KL_OFF + 64 * AT_S;
constexpr int VL_OFF   = VH_OFF + 64 * AT_S;
constexpr int AT_ELEMS = VL_OFF + 64 * AT_S;    // 36864 bf16
constexpr int AT_SMEM  = AT_ELEMS * 2 + 256;    // + mask

__global__ __launch_bounds__(256, 2)
void attn_mma(const __nv_bfloat16* __restrict__ Qh, const __nv_bfloat16* __restrict__ Ql,
              const __nv_bfloat16* __restrict__ Kh, const __nv_bfloat16* __restrict__ Kl,
              const __nv_bfloat16* __restrict__ Vh, const __nv_bfloat16* __restrict__ Vl,
              const int* __restrict__ mask, float* __restrict__ O)
{
    extern __shared__ char smraw[];
    __nv_bfloat16* sq = (__nv_bfloat16*)smraw;
    int* msk = (int*)(smraw + AT_ELEMS * 2);
    const uint32_t sbase = smem_u32(sq);

    const int tid  = threadIdx.x;
    const int lane = tid & 31;
    const int wid  = tid >> 5;
    const int quad = lane >> 2;
    const int ql   = lane & 3;
    const int grp  = lane >> 3;
    const int b    = blockIdx.y >> 4;
    const int h    = blockIdx.y & 15;
    const int q0   = blockIdx.x * 128;
    const int mrow = wid * 16;

    const size_t qbase = (size_t)(b * SEQ + q0) * DIM + h * DK;

    // Q tile 128x64 hi/lo
    {
        const int ch = tid & 7;
#pragma unroll
        for (int it = 0; it < 4; ++it) {
            int r = (it * 256 + tid) >> 3;
            *(uint4*)&sq[r * AT_S + ch * 8] =
                *(const uint4*)&Qh[qbase + (size_t)r * DIM + ch * 8];
            *(uint4*)&sq[QL_OFF + r * AT_S + ch * 8] =
                *(const uint4*)&Ql[qbase + (size_t)r * DIM + ch * 8];
        }
    }

    float m_i[2] = {-1e30f, -1e30f};
    float l_i[2] = {0.f, 0.f};
    float acc_o[8][4];
#pragma unroll
    for (int nt = 0; nt < 8; ++nt)
#pragma unroll
        for (int i = 0; i < 4; ++i) acc_o[nt][i] = 0.f;

    for (int kb = 0; kb < SEQ; kb += 64) {
        __syncthreads();
        // K tile 64x64 hi/lo ; V tile loaded transposed -> [dk][s]
        {
            const size_t kbase = (size_t)(b * SEQ + kb) * DIM + h * DK;
            const int ch = tid & 7;
#pragma unroll
            for (int it = 0; it < 2; ++it) {
                int r = (it * 256 + tid) >> 3;
                *(uint4*)&sq[KH_OFF + r * AT_S + ch * 8] =
                    *(const uint4*)&Kh[kbase + (size_t)r * DIM + ch * 8];
                *(uint4*)&sq[KL_OFF + r * AT_S + ch * 8] =
                    *(const uint4*)&Kl[kbase + (size_t)r * DIM + ch * 8];
                uint4 vh4 = *(const uint4*)&Vh[kbase + (size_t)r * DIM + ch * 8];
                uint4 vl4 = *(const uint4*)&Vl[kbase + (size_t)r * DIM + ch * 8];
                const __nv_bfloat16* ph = (const __nv_bfloat16*)&vh4;
                const __nv_bfloat16* pl = (const __nv_bfloat16*)&vl4;
#pragma unroll
                for (int i = 0; i < 8; ++i) {
                    sq[VH_OFF + (ch * 8 + i) * AT_S + r] = ph[i];
                    sq[VL_OFF + (ch * 8 + i) * AT_S + r] = pl[i];
                }
            }
            if (tid < 64) msk[tid] = mask[b * SEQ + kb + tid];
        }
        __syncthreads();

        // ---- S = Q @ K^T (3-term split) ----
        float s[8][4];
#pragma unroll
        for (int nt = 0; nt < 8; ++nt)
#pragma unroll
            for (int i = 0; i < 4; ++i) s[nt][i] = 0.f;

#pragma unroll
        for (int ks = 0; ks < 4; ++ks) {
            uint32_t ah[4], al[4];
            {
                int row = mrow + (lane & 15);
                int col = ks * 16 + ((lane >> 4) << 3);
                uint32_t ad = sbase + (uint32_t)(row * AT_S + col) * 2;
                LDSM4(ah, ad);
                LDSM4(al, ad + QL_OFF * 2);
            }
            uint32_t bh[8][2], bl[8][2];
#pragma unroll
            for (int np = 0; np < 4; ++np) {
                int nrow = np * 16 + ((grp >> 1) << 3) + (lane & 7);
                int kcol = ks * 16 + ((grp & 1) << 3);
                uint32_t bd = sbase + (uint32_t)(KH_OFF + nrow * AT_S + kcol) * 2;
                uint32_t q[4];
                LDSM4(q, bd);
                bh[np*2][0] = q[0]; bh[np*2][1] = q[1];
                bh[np*2+1][0] = q[2]; bh[np*2+1][1] = q[3];
                LDSM4(q, bd + (KL_OFF - KH_OFF) * 2);
                bl[np*2][0] = q[0]; bl[np*2][1] = q[1];
                bl[np*2+1][0] = q[2]; bl[np*2+1][1] = q[3];
            }
#pragma unroll
            for (int nt = 0; nt < 8; ++nt) {
                MMA16816(s[nt], ah, bh[nt]);
                MMA16816(s[nt], ah, bl[nt]);
                MMA16816(s[nt], al, bh[nt]);
            }
        }

        // ---- mask ----
        const int c0 = 2 * ql;
#pragma unroll
        for (int nt = 0; nt < 8; ++nt) {
            if (msk[nt * 8 + c0]     == 0) { s[nt][0] = -1e9f; s[nt][2] = -1e9f; }
            if (msk[nt * 8 + c0 + 1] == 0) { s[nt][1] = -1e9f; s[nt][3] = -1e9f; }
        }

        // ---- online softmax (rows quad, quad+8; reduce over ql lanes) ----
        float mxA = -1e30f, mxB = -1e30f;
#pragma unroll
        for (int nt = 0; nt < 8; ++nt) {
            mxA = fmaxf(mxA, fmaxf(s[nt][0], s[nt][1]));
            mxB = fmaxf(mxB, fmaxf(s[nt][2], s[nt][3]));
        }
#pragma unroll
        for (int o = 1; o <= 2; o <<= 1) {
            mxA = fmaxf(mxA, __shfl_xor_sync(0xffffffffu, mxA, o));
            mxB = fmaxf(mxB, __shfl_xor_sync(0xffffffffu, mxB, o));
        }
        const float mnA = fmaxf(m_i[0], mxA);
        const float mnB = fmaxf(m_i[1], mxB);
        const float sclA = fexp(m_i[0] - mnA);
        const float sclB = fexp(m_i[1] - mnB);
        m_i[0] = mnA; m_i[1] = mnB;

        float smA = 0.f, smB = 0.f;
#pragma unroll
        for (int nt = 0; nt < 8; ++nt) {
            s[nt][0] = fexp(s[nt][0] - mnA);
            s[nt][1] = fexp(s[nt][1] - mnA);
            s[nt][2] = fexp(s[nt][2] - mnB);
            s[nt][3] = fexp(s[nt][3] - mnB);
            smA += s[nt][0] + s[nt][1];
            smB += s[nt][2] + s[nt][3];
        }
#pragma unroll
        for (int o = 1; o <= 2; o <<= 1) {
            smA += __shfl_xor_sync(0xffffffffu, smA, o);
            smB += __shfl_xor_sync(0xffffffffu, smB, o);
        }
        l_i[0] = l_i[0] * sclA + smA;
        l_i[1] = l_i[1] * sclB + smB;
#pragma unroll
        for (int nt = 0; nt < 8; ++nt) {
            acc_o[nt][0] *= sclA; acc_o[nt][1] *= sclA;
            acc_o[nt][2] *= sclB; acc_o[nt][3] *= sclB;
        }

        // ---- ctx += P @ V  (P plain bf16; V hi+lo) ----
#pragma unroll
        for (int ks = 0; ks < 4; ++ks) {
            uint32_t aP[4];
            aP[0] = fpack2(s[2*ks  ][0], s[2*ks  ][1]);
            aP[1] = fpack2(s[2*ks  ][2], s[2*ks  ][3]);
            aP[2] = fpack2(s[2*ks+1][0], s[2*ks+1][1]);
            aP[3] = fpack2(s[2*ks+1][2], s[2*ks+1][3]);
            uint32_t bvh[8][2], bvl[8][2];
#pragma unroll
            for (int np = 0; np < 4; ++np) {
                int nrow = np * 16 + ((grp >> 1) << 3) + (lane & 7);  // dk
                int kcol = ks * 16 + ((grp & 1) << 3);                // keys
                uint32_t bd = sbase + (uint32_t)(VH_OFF + nrow * AT_S + kcol) * 2;
                uint32_t q[4];
                LDSM4(q, bd);
                bvh[np*2][0] = q[0]; bvh[np*2][1] = q[1];
                bvh[np*2+1][0] = q[2]; bvh[np*2+1][1] = q[3];
                LDSM4(q, bd + (VL_OFF - VH_OFF) * 2);
                bvl[np*2][0] = q[0]; bvl[np*2][1] = q[1];
                bvl[np*2+1][0] = q[2]; bvl[np*2+1][1] = q[3];
            }
#pragma unroll
            for (int nt = 0; nt < 8; ++nt) {
                MMA16816(acc_o[nt], aP, bvh[nt]);
                MMA16816(acc_o[nt], aP, bvl[nt]);
            }
        }
    }

    // ---- epilogue ----
    const float invA = 1.f / l_i[0];
    const float invB = 1.f / l_i[1];
    const size_t obase = (size_t)(b * SEQ + q0 + mrow) * DIM + h * DK;
#pragma unroll
    for (int nt = 0; nt < 8; ++nt) {
        const int col = nt * 8 + 2 * ql;
        float2 vA = make_float2(acc_o[nt][0] * invA, acc_o[nt][1] * invA);
        float2 vB = make_float2(acc_o[nt][2] * invB, acc_o[nt][3] * invB);
        *(float2*)&O[obase + (size_t)quad * DIM + col]       = vA;
        *(float2*)&O[obase + (size_t)(quad + 8) * DIM + col] = vB;
    }
}

// ===========================================================================
// LayerNorm over last dim (1024). One block per row, 256 threads x float4.
// ===========================================================================
__global__ __launch_bounds__(256)
void layernorm_kernel(const float* __restrict__ in, const float* __restrict__ g,
                      const float* __restrict__ b, float* __restrict__ out)
{
    const int row = blockIdx.x;
    const int tid = threadIdx.x;
    const float4 v = ((const float4*)(in + (size_t)row * DIM))[tid];
    float s  = v.x + v.y + v.z + v.w;
    float sq = fmaf(v.x, v.x, fmaf(v.y, v.y, fmaf(v.z, v.z, v.w * v.w)));

#pragma unroll
    for (int o = 16; o >= 1; o >>= 1) {
        s  += __shfl_xor_sync(0xffffffffu, s,  o);
        sq += __shfl_xor_sync(0xffffffffu, sq, o);
    }
    __shared__ float ss[8], ssq[8];
    const int warp = tid >> 5, lane = tid & 31;
    if (lane == 0) { ss[warp] = s; ssq[warp] = sq; }
    __syncthreads();
    if (warp == 0) {
        float a = (lane < 8) ? ss[lane]  : 0.f;
        float q = (lane < 8) ? ssq[lane] : 0.f;
#pragma unroll
        for (int o = 4; o >= 1; o >>= 1) {
            a += __shfl_xor_sync(0xffffffffu, a, o);
            q += __shfl_xor_sync(0xffffffffu, q, o);
        }
        if (lane == 0) { ss[0] = a; ssq[0] = q; }
    }
    __syncthreads();
    const float mu   = ss[0]  * (1.f / DIM);
    const float var  = ssq[0] * (1.f / DIM) - mu * mu;
    const float rstd = rsqrtf(var + 1e-5f);

    const float4 gg = ((const float4*)g)[tid];
    const float4 bb = ((const float4*)b)[tid];
    float4 o;
    o.x = (v.x - mu) * rstd * gg.x + bb.x;
    o.y = (v.y - mu) * rstd * gg.y + bb.y;
    o.z = (v.z - mu) * rstd * gg.z + bb.z;
    o.w = (v.w - mu) * rstd * gg.w + bb.w;
    ((float4*)(out + (size_t)row * DIM))[tid] = o;
}

// ---------------------------------------------------------------------------
static void* sym_addr(const void* s)
{
    void* p = nullptr;
    cudaGetSymbolAddress(&p, s);
    return p;
}

extern "C" void kernel_launch(void* const* d_in, const int* in_sizes, int n_in,
                              void* d_out, int out_size)
{
    const float* x     = (const float*)d_in[0];
    const int*   mask  = (const int*)  d_in[1];
    const float* Wq    = (const float*)d_in[2];
    const float* Wk    = (const float*)d_in[3];
    const float* Wv    = (const float*)d_in[4];
    const float* Wo    = (const float*)d_in[5];
    const float* W1    = (const float*)d_in[6];
    const float* b1    = (const float*)d_in[7];
    const float* W2    = (const float*)d_in[8];
    const float* b2    = (const float*)d_in[9];
    const float* ln1_g = (const float*)d_in[10];
    const float* ln1_b = (const float*)d_in[11];
    const float* ln2_g = (const float*)d_in[12];
    const float* ln2_b = (const float*)d_in[13];
    float* out = (float*)d_out;

    float* Cx  = (float*)sym_addr(g_ctx);
    float* T1  = (float*)sym_addr(g_t1);
    float* Hb  = (float*)sym_addr(g_h);
    float* Ff  = (float*)sym_addr(g_ff);
    __nv_bfloat16* qh = (__nv_bfloat16*)sym_addr(g_Qh);
    __nv_bfloat16* qlp= (__nv_bfloat16*)sym_addr(g_Ql);
    __nv_bfloat16* kh = (__nv_bfloat16*)sym_addr(g_Kh);
    __nv_bfloat16* kl = (__nv_bfloat16*)sym_addr(g_Kl);
    __nv_bfloat16* vh = (__nv_bfloat16*)sym_addr(g_Vh);
    __nv_bfloat16* vl = (__nv_bfloat16*)sym_addr(g_Vl);
    __nv_bfloat16* wh = (__nv_bfloat16*)sym_addr(g_wh);
    __nv_bfloat16* wl = (__nv_bfloat16*)sym_addr(g_wl);

    static bool attr_set = false;
    if (!attr_set) {
        cudaFuncSetAttribute(attn_mma,
            cudaFuncAttributeMaxDynamicSharedMemorySize, AT_SMEM);
        cudaFuncSetAttribute(hgemm<false, false, false, true>,
            cudaFuncAttributeMaxDynamicSharedMemorySize, HG_SMEM);
        cudaFuncSetAttribute(hgemm<false, false, true, false>,
            cudaFuncAttributeMaxDynamicSharedMemorySize, HG_SMEM);
        cudaFuncSetAttribute(hgemm<true, true, false, false>,
            cudaFuncAttributeMaxDynamicSharedMemorySize, HG_SMEM);
        cudaFuncSetAttribute(hgemm<true, false, true, false>,
            cudaFuncAttributeMaxDynamicSharedMemorySize, HG_SMEM);
        attr_set = true;
    }

    const dim3 blk(256);

    // ---- weight pre-split ----
    wsplit<<<dim3(DIM / 32, DIM / 32), blk>>>(Wq, DIM, DIM, wh + WOFF_Q, wl + WOFF_Q);
    wsplit<<<dim3(DIM / 32, DIM / 32), blk>>>(Wk, DIM, DIM, wh + WOFF_K, wl + WOFF_K);
    wsplit<<<dim3(DIM / 32, DIM / 32), blk>>>(Wv, DIM, DIM, wh + WOFF_V, wl + WOFF_V);
    wsplit<<<dim3(DIM / 32, DIM / 32), blk>>>(Wo, DIM, DIM, wh + WOFF_O, wl + WOFF_O);
    wsplit<<<dim3(DFF / 32, DIM / 32), blk>>>(W1, DIM, DFF, wh + WOFF_W1, wl + WOFF_W1);
    wsplit<<<dim3(DIM / 32, DFF / 32), blk>>>(W2, DFF, DIM, wh + WOFF_W2, wl + WOFF_W2);

    const dim3 gD  (DIM / 64, TOK / 128);    // (16, 64)
    const dim3 gDFF(DFF / 64, TOK / 128);    // (64, 64)

    // projections -> split-bf16 outputs (1/sqrt(dk)=0.125 folded into Q)
    hgemm<false, false, false, true><<<gD, blk, HG_SMEM>>>(
        x, wh + WOFF_Q, wl + WOFF_Q, nullptr, nullptr, nullptr, qh, qlp, DIM, DIM, 0.125f);
    hgemm<false, false, false, true><<<gD, blk, HG_SMEM>>>(
        x, wh + WOFF_K, wl + WOFF_K, nullptr, nullptr, nullptr, kh, kl, DIM, DIM, 1.0f);
    hgemm<false, false, false, true><<<gD, blk, HG_SMEM>>>(
        x, wh + WOFF_V, wl + WOFF_V, nullptr, nullptr, nullptr, vh, vl, DIM, DIM, 1.0f);

    // attention (tensorized)
    attn_mma<<<dim3(SEQ / 128, NB * NH), blk, AT_SMEM>>>(
        qh, qlp, kh, kl, vh, vl, mask, Cx);

    // output projection + residual, LN1
    hgemm<false, false, true, false><<<gD, blk, HG_SMEM>>>(
        Cx, wh + WOFF_O, wl + WOFF_O, nullptr, x, T1, nullptr, nullptr, DIM, DIM, 1.0f);
    layernorm_kernel<<<TOK, blk>>>(T1, ln1_g, ln1_b, Hb);

    // FFN + residual, LN2
    hgemm<true, true, false, false><<<gDFF, blk, HG_SMEM>>>(
        Hb, wh + WOFF_W1, wl + WOFF_W1, b1, nullptr, Ff, nullptr, nullptr, DFF, DIM, 1.0f);
    hgemm<true, false, true, false><<<gD, blk, HG_SMEM>>>(
        Ff, wh + WOFF_W2, wl + WOFF_W2, b2, Hb, T1, nullptr, nullptr, DIM, DFF, 1.0f);
    layernorm_kernel<<<TOK, blk>>>(T1, ln2_g, ln2_b, out);
}

// round 16
// speedup vs baseline: 2.6490x; 1.0905x over previous
#include <cuda_runtime.h>
#include <cuda_bf16.h>
#include <cstdint>

// ---------------------------------------------------------------------------
// EncoderLayer: B=4 S=2048 D=1024 H=16 dk=64 Dff=4096, fp32 in/out.
// GEMMs + attention on mma.sync bf16 (HMMA) with split-bf16 error compensation.
// Attention v2: cp.async double-buffered K/V, ldmatrix.trans for V (no scalar
// transpose), Q fragments register-resident. exp via FMA-pipe polynomial.
// ---------------------------------------------------------------------------

constexpr int NB  = 4;
constexpr int SEQ = 2048;
constexpr int DIM = 1024;
constexpr int NH  = 16;
constexpr int DK  = 64;
constexpr int DFF = 4096;
constexpr int TOK = NB * SEQ;          // 8192

// scratch (device globals: allocation-free per harness rules)
__device__ float g_ctx[TOK * DIM];
__device__ float g_t1 [TOK * DIM];
__device__ float g_h  [TOK * DIM];
__device__ float g_ff [(size_t)TOK * DFF];
__device__ __nv_bfloat16 g_Qh[TOK * DIM], g_Ql[TOK * DIM];
__device__ __nv_bfloat16 g_Kh[TOK * DIM], g_Kl[TOK * DIM];
__device__ __nv_bfloat16 g_Vh[TOK * DIM], g_Vl[TOK * DIM];
// pre-split weights, [N][K] layout, bf16 hi/lo.
constexpr size_t WOFF_Q  = 0;
constexpr size_t WOFF_K  = 1ull << 20;
constexpr size_t WOFF_V  = 2ull << 20;
constexpr size_t WOFF_O  = 3ull << 20;
constexpr size_t WOFF_W1 = 4ull << 20;
constexpr size_t WOFF_W2 = 8ull << 20;
__device__ __nv_bfloat16 g_wh[12ull << 20];
__device__ __nv_bfloat16 g_wl[12ull << 20];

// ===========================================================================
// helpers
// ===========================================================================
__device__ __forceinline__ uint32_t smem_u32(const void* p) {
    uint32_t a;
    asm("{ .reg .u64 t; cvta.to.shared.u64 t, %1; cvt.u32.u64 %0, t; }"
        : "=r"(a) : "l"(p));
    return a;
}

#define LDSM4(r, addr) \
    asm volatile("ldmatrix.sync.aligned.m8n8.x4.shared.b16 {%0,%1,%2,%3}, [%4];" \
        : "=r"((r)[0]), "=r"((r)[1]), "=r"((r)[2]), "=r"((r)[3]) : "r"(addr))

#define LDSM4T(r, addr) \
    asm volatile("ldmatrix.sync.aligned.m8n8.x4.trans.shared.b16 {%0,%1,%2,%3}, [%4];" \
        : "=r"((r)[0]), "=r"((r)[1]), "=r"((r)[2]), "=r"((r)[3]) : "r"(addr))

#define MMA16816(d, a, b) \
    asm volatile("mma.sync.aligned.m16n8k16.row.col.f32.bf16.bf16.f32 " \
        "{%0,%1,%2,%3}, {%4,%5,%6,%7}, {%8,%9}, {%0,%1,%2,%3};" \
        : "+f"((d)[0]), "+f"((d)[1]), "+f"((d)[2]), "+f"((d)[3]) \
        : "r"((a)[0]), "r"((a)[1]), "r"((a)[2]), "r"((a)[3]), \
          "r"((b)[0]), "r"((b)[1]))

#define CPASYNC16(dst, src) \
    asm volatile("cp.async.cg.shared.global [%0], [%1], 16;" \
                 :: "r"((uint32_t)(dst)), "l"(src) : "memory")
#define CPASYNC_COMMIT() asm volatile("cp.async.commit_group;" ::: "memory")
#define CPASYNC_WAIT0()  asm volatile("cp.async.wait_group 0;" ::: "memory")

__device__ __forceinline__ uint32_t bfpack(__nv_bfloat16 a, __nv_bfloat16 b) {
    __nv_bfloat162 t; t.x = a; t.y = b;
    return *reinterpret_cast<uint32_t*>(&t);
}
__device__ __forceinline__ uint32_t fpack2(float a, float b) {
    return bfpack(__float2bfloat16(a), __float2bfloat16(b));
}
__device__ __forceinline__ void bsplit(float v, __nv_bfloat16& h, __nv_bfloat16& l) {
    h = __float2bfloat16(v);
    l = __float2bfloat16(v - __bfloat162float(h));
}

// fast exp on the FMA pipe
__device__ __forceinline__ float fexp(float x) {
    x = fmaxf(x, -87.f);
    float t = fmaf(x, 1.4426950408889634f, 12582912.f);
    int   n = __float_as_int(t) - 0x4B400000;
    float f = fmaf(x, 1.4426950408889634f, -(t - 12582912.f));
    float p =             1.3333558146e-3f;
    p = fmaf(p, f, 9.6181291076e-3f);
    p = fmaf(p, f, 5.5504108664e-2f);
    p = fmaf(p, f, 2.4022650696e-1f);
    p = fmaf(p, f, 6.9314718056e-1f);
    p = fmaf(p, f, 1.0f);
    return __int_as_float(__float_as_int(p) + (n << 23));
}

// ===========================================================================
// Weight pre-pass: W[K,N] fp32 -> hi/lo bf16 in [N,K] layout (transposed).
// ===========================================================================
__global__ __launch_bounds__(256)
void wsplit(const float* __restrict__ W, int K, int N,
            __nv_bfloat16* __restrict__ oh, __nv_bfloat16* __restrict__ ol)
{
    __shared__ float t[32][33];
    const int k0 = blockIdx.y * 32, n0 = blockIdx.x * 32;
    const int tx = threadIdx.x & 31, ty = threadIdx.x >> 5;
#pragma unroll
    for (int j = ty; j < 32; j += 8)
        t[j][tx] = W[(size_t)(k0 + j) * N + n0 + tx];
    __syncthreads();
#pragma unroll
    for (int j = ty; j < 32; j += 8) {
        float v = t[tx][j];
        __nv_bfloat16 h, l; bsplit(v, h, l);
        oh[(size_t)(n0 + j) * K + k0 + tx] = h;
        ol[(size_t)(n0 + j) * K + k0 + tx] = l;
    }
}

// ===========================================================================
// HMMA GEMM (unchanged from R14-passing version).
// ===========================================================================
constexpr int HG_STAGE  = 30720;
constexpr int HG_SMEM   = 2 * HG_STAGE;
constexpr int OFF_AL    = 10240;
constexpr int OFF_BH    = 20480;
constexpr int OFF_BL    = 25600;

template<bool BIAS, bool RELU, bool RES, bool SPLITOUT>
__global__ __launch_bounds__(256)
void hgemm(const float* __restrict__ A,
           const __nv_bfloat16* __restrict__ Bhg,
           const __nv_bfloat16* __restrict__ Blg,
           const float* __restrict__ bias, const float* __restrict__ res,
           float* __restrict__ C,
           __nv_bfloat16* __restrict__ Ch, __nv_bfloat16* __restrict__ Cl,
           int N, int K, float alpha)
{
    extern __shared__ char smem[];
    const uint32_t sbase = smem_u32(smem);

    const int tid    = threadIdx.x;
    const int lane   = tid & 31;
    const int wid    = tid >> 5;
    const int warp_m = wid & 3;
    const int warp_n = wid >> 2;
    const int mbase  = warp_m * 32;
    const int nbase  = warp_n * 32;
    const int row0   = blockIdx.y * 128;
    const int col0   = blockIdx.x * 64;

    const int nk = K >> 5;

    float acc[2][4][4];
#pragma unroll
    for (int mt = 0; mt < 2; ++mt)
#pragma unroll
        for (int nt = 0; nt < 4; ++nt)
#pragma unroll
            for (int i = 0; i < 4; ++i) acc[mt][nt][i] = 0.f;

    float4 pa[4];
    uint2  pbh[2], pbl[2];
    const float* Ab = A + (size_t)row0 * K;

#pragma unroll
    for (int it = 0; it < 4; ++it) {
        int idx = it * 256 + tid, r = idx >> 3, c4 = idx & 7;
        pa[it] = *(const float4*)&Ab[(size_t)r * K + c4 * 4];
    }
#pragma unroll
    for (int it = 0; it < 2; ++it) {
        int idx = it * 256 + tid, r = idx >> 3, c4 = idx & 7;
        pbh[it] = *(const uint2*)&Bhg[(size_t)(col0 + r) * K + c4 * 4];
        pbl[it] = *(const uint2*)&Blg[(size_t)(col0 + r) * K + c4 * 4];
    }
    {
        char* st = smem;
#pragma unroll
        for (int it = 0; it < 4; ++it) {
            int idx = it * 256 + tid, r = idx >> 3, c4 = idx & 7;
            __nv_bfloat16 h0,h1,h2,h3,l0,l1,l2,l3;
            bsplit(pa[it].x,h0,l0); bsplit(pa[it].y,h1,l1);
            bsplit(pa[it].z,h2,l2); bsplit(pa[it].w,h3,l3);
            uint32_t off = (uint32_t)(r * 40 + c4 * 4) * 2;
            uint2 hp; hp.x = bfpack(h0,h1); hp.y = bfpack(h2,h3);
            uint2 lp; lp.x = bfpack(l0,l1); lp.y = bfpack(l2,l3);
            *(uint2*)(st + off)           = hp;
            *(uint2*)(st + OFF_AL + off)  = lp;
        }
#pragma unroll
        for (int it = 0; it < 2; ++it) {
            int idx = it * 256 + tid, r = idx >> 3, c4 = idx & 7;
            uint32_t off = (uint32_t)(r * 40 + c4 * 4) * 2;
            *(uint2*)(st + OFF_BH + off) = pbh[it];
            *(uint2*)(st + OFF_BL + off) = pbl[it];
        }
    }
    __syncthreads();

    for (int kb = 0; kb < nk; ++kb) {
        if (kb + 1 < nk) {
            const float* Ap = Ab + ((kb + 1) << 5);
#pragma unroll
            for (int it = 0; it < 4; ++it) {
                int idx = it * 256 + tid, r = idx >> 3, c4 = idx & 7;
                pa[it] = *(const float4*)&Ap[(size_t)r * K + c4 * 4];
            }
            const size_t bofs = ((size_t)(kb + 1) << 5);
#pragma unroll
            for (int it = 0; it < 2; ++it) {
                int idx = it * 256 + tid, r = idx >> 3, c4 = idx & 7;
                pbh[it] = *(const uint2*)&Bhg[(size_t)(col0 + r) * K + bofs + c4 * 4];
                pbl[it] = *(const uint2*)&Blg[(size_t)(col0 + r) * K + bofs + c4 * 4];
            }
        }

        const uint32_t sb = sbase + (uint32_t)(kb & 1) * HG_STAGE;
#pragma unroll
        for (int ks = 0; ks < 2; ++ks) {
            uint32_t ah[2][4], al[2][4], bh[4][2], bl[4][2];
#pragma unroll
            for (int mt = 0; mt < 2; ++mt) {
                int row = mbase + mt * 16 + (lane & 15);
                int col = ks * 16 + ((lane >> 4) << 3);
                uint32_t ad = sb + (uint32_t)(row * 40 + col) * 2;
                LDSM4(ah[mt], ad);
                LDSM4(al[mt], ad + OFF_AL);
            }
#pragma unroll
            for (int np = 0; np < 2; ++np) {
                int grp  = lane >> 3;
                int nrow = nbase + np * 16 + ((grp >> 1) << 3) + (lane & 7);
                int kcol = ks * 16 + ((grp & 1) << 3);
                uint32_t bd = sb + OFF_BH + (uint32_t)(nrow * 40 + kcol) * 2;
                uint32_t q[4];
                LDSM4(q, bd);
                bh[np*2][0] = q[0]; bh[np*2][1] = q[1];
                bh[np*2+1][0] = q[2]; bh[np*2+1][1] = q[3];
                LDSM4(q, bd + (OFF_BL - OFF_BH));
                bl[np*2][0] = q[0]; bl[np*2][1] = q[1];
                bl[np*2+1][0] = q[2]; bl[np*2+1][1] = q[3];
            }
#pragma unroll
            for (int mt = 0; mt < 2; ++mt)
#pragma unroll
                for (int nt = 0; nt < 4; ++nt) {
                    MMA16816(acc[mt][nt], ah[mt], bh[nt]);
                    MMA16816(acc[mt][nt], ah[mt], bl[nt]);
                    MMA16816(acc[mt][nt], al[mt], bh[nt]);
                }
        }

        if (kb + 1 < nk) {
            char* st = smem + ((kb + 1) & 1) * HG_STAGE;
#pragma unroll
            for (int it = 0; it < 4; ++it) {
                int idx = it * 256 + tid, r = idx >> 3, c4 = idx & 7;
                __nv_bfloat16 h0,h1,h2,h3,l0,l1,l2,l3;
                bsplit(pa[it].x,h0,l0); bsplit(pa[it].y,h1,l1);
                bsplit(pa[it].z,h2,l2); bsplit(pa[it].w,h3,l3);
                uint32_t off = (uint32_t)(r * 40 + c4 * 4) * 2;
                uint2 hp; hp.x = bfpack(h0,h1); hp.y = bfpack(h2,h3);
                uint2 lp; lp.x = bfpack(l0,l1); lp.y = bfpack(l2,l3);
                *(uint2*)(st + off)          = hp;
                *(uint2*)(st + OFF_AL + off) = lp;
            }
#pragma unroll
            for (int it = 0; it < 2; ++it) {
                int idx = it * 256 + tid, r = idx >> 3, c4 = idx & 7;
                uint32_t off = (uint32_t)(r * 40 + c4 * 4) * 2;
                *(uint2*)(st + OFF_BH + off) = pbh[it];
                *(uint2*)(st + OFF_BL + off) = pbl[it];
            }
        }
        __syncthreads();
    }

    const int quad  = lane >> 2;
    const int qlane = lane & 3;
#pragma unroll
    for (int mt = 0; mt < 2; ++mt) {
#pragma unroll
        for (int nt = 0; nt < 4; ++nt) {
            const int cg = col0 + nbase + nt * 8 + (qlane << 1);
#pragma unroll
            for (int h = 0; h < 2; ++h) {
                const int rg = row0 + mbase + mt * 16 + quad + h * 8;
                float2 v;
                v.x = acc[mt][nt][h * 2 + 0] * alpha;
                v.y = acc[mt][nt][h * 2 + 1] * alpha;
                if (BIAS) {
                    float2 bb = *(const float2*)&bias[cg];
                    v.x += bb.x; v.y += bb.y;
                }
                if (RES) {
                    float2 rr = *(const float2*)&res[(size_t)rg * N + cg];
                    v.x += rr.x; v.y += rr.y;
                }
                if (RELU) { v.x = fmaxf(v.x, 0.f); v.y = fmaxf(v.y, 0.f); }
                if (SPLITOUT) {
                    __nv_bfloat16 hx, lx, hy, ly;
                    bsplit(v.x, hx, lx); bsplit(v.y, hy, ly);
                    *(uint32_t*)&Ch[(size_t)rg * N + cg] = bfpack(hx, hy);
                    *(uint32_t*)&Cl[(size_t)rg * N + cg] = bfpack(lx, ly);
                } else {
                    *(float2*)&C[(size_t)rg * N + cg] = v;
                }
            }
        }
    }
}

// ===========================================================================
// Tensorized flash attention v2.
// Grid (SEQ/128, NB*NH), 256 thr = 8 warps x 16 query rows. Key tile = 64.
// cp.async double-buffered K/V (+mask); V row-major + ldmatrix.trans;
// Q fragments register-resident.
// Stage layout (bytes): KH 0, KL 9216, VH 18432, VL 27648, MSK 36864; 37120/stage.
// ===========================================================================
constexpr int AT_S    = 72;
constexpr int STG_KL  = 9216;
constexpr int STG_VH  = 18432;
constexpr int STG_VL  = 27648;
constexpr int STG_MSK = 36864;
constexpr int STG_B   = 37120;
constexpr int AT_SMEM = 2 * STG_B;      // 74240

__global__ __launch_bounds__(256, 2)
void attn_mma(const __nv_bfloat16* __restrict__ Qh, const __nv_bfloat16* __restrict__ Ql,
              const __nv_bfloat16* __restrict__ Kh, const __nv_bfloat16* __restrict__ Kl,
              const __nv_bfloat16* __restrict__ Vh, const __nv_bfloat16* __restrict__ Vl,
              const int* __restrict__ mask, float* __restrict__ O)
{
    extern __shared__ char smraw[];
    const uint32_t sbase = smem_u32(smraw);

    const int tid  = threadIdx.x;
    const int lane = tid & 31;
    const int wid  = tid >> 5;
    const int quad = lane >> 2;
    const int ql   = lane & 3;
    const int grp  = lane >> 3;
    const int b    = blockIdx.y >> 4;
    const int h    = blockIdx.y & 15;
    const int q0   = blockIdx.x * 128;
    const int mrow = wid * 16;
    const int ch   = tid & 7;

    const size_t qbase = (size_t)(b * SEQ + q0) * DIM + h * DK;
    const size_t kvb0  = (size_t)(b * SEQ) * DIM + h * DK;

    // ---- stage Q into buffer 0 region, extract fragments to registers ----
    {
        __nv_bfloat16* sq = (__nv_bfloat16*)smraw;
#pragma unroll
        for (int it = 0; it < 4; ++it) {
            int r = (it * 256 + tid) >> 3;
            *(uint4*)&sq[r * AT_S + ch * 8] =
                *(const uint4*)&Qh[qbase + (size_t)r * DIM + ch * 8];
            *(uint4*)&sq[9216 + r * AT_S + ch * 8] =
                *(const uint4*)&Ql[qbase + (size_t)r * DIM + ch * 8];
        }
    }
    __syncthreads();
    uint32_t qfh[4][4], qfl[4][4];
    {
        int row = mrow + (lane & 15);
        int col = (lane >> 4) << 3;
#pragma unroll
        for (int ks = 0; ks < 4; ++ks) {
            uint32_t ad = sbase + (uint32_t)(row * AT_S + ks * 16 + col) * 2;
            LDSM4(qfh[ks], ad);
            LDSM4(qfl[ks], ad + 18432);
        }
    }
    __syncthreads();   // Q fragments extracted; buffer 0 now reusable

    // ---- issue tile 0 ----
    {
        const size_t kbase = kvb0;   // kb = 0
        const uint32_t stg = sbase;
#pragma unroll
        for (int it = 0; it < 2; ++it) {
            int r = (it * 256 + tid) >> 3;
            uint32_t d = (uint32_t)(r * AT_S + ch * 8) * 2;
            const size_t g = kbase + (size_t)r * DIM + ch * 8;
            CPASYNC16(stg + d,           &Kh[g]);
            CPASYNC16(stg + STG_KL + d,  &Kl[g]);
            CPASYNC16(stg + STG_VH + d,  &Vh[g]);
            CPASYNC16(stg + STG_VL + d,  &Vl[g]);
        }
        if (tid < 16) CPASYNC16(stg + STG_MSK + tid * 16, &mask[b * SEQ + tid * 4]);
        CPASYNC_COMMIT();
    }

    float m_i[2] = {-1e30f, -1e30f};
    float l_i[2] = {0.f, 0.f};
    float acc_o[8][4];
#pragma unroll
    for (int nt = 0; nt < 8; ++nt)
#pragma unroll
        for (int i = 0; i < 4; ++i) acc_o[nt][i] = 0.f;

    const int NT = SEQ / 64;   // 32 tiles
    for (int t = 0; t < NT; ++t) {
        CPASYNC_WAIT0();
        __syncthreads();       // tile t visible to all; compute(t-1) done by all

        // prefetch tile t+1 (overlaps compute below)
        if (t + 1 < NT) {
            const size_t kbase = kvb0 + (size_t)((t + 1) * 64) * DIM;
            const uint32_t stg = sbase + ((t + 1) & 1) * STG_B;
#pragma unroll
            for (int it = 0; it < 2; ++it) {
                int r = (it * 256 + tid) >> 3;
                uint32_t d = (uint32_t)(r * AT_S + ch * 8) * 2;
                const size_t g = kbase + (size_t)r * DIM + ch * 8;
                CPASYNC16(stg + d,           &Kh[g]);
                CPASYNC16(stg + STG_KL + d,  &Kl[g]);
                CPASYNC16(stg + STG_VH + d,  &Vh[g]);
                CPASYNC16(stg + STG_VL + d,  &Vl[g]);
            }
            if (tid < 16)
                CPASYNC16(stg + STG_MSK + tid * 16,
                          &mask[b * SEQ + (t + 1) * 64 + tid * 4]);
            CPASYNC_COMMIT();
        }

        const uint32_t st = sbase + (t & 1) * STG_B;
        const int* msk = (const int*)(smraw + (t & 1) * STG_B + STG_MSK);

        // ---- S = Q @ K^T (3-term split) ----
        float s[8][4];
#pragma unroll
        for (int nt = 0; nt < 8; ++nt)
#pragma unroll
            for (int i = 0; i < 4; ++i) s[nt][i] = 0.f;

#pragma unroll
        for (int ks = 0; ks < 4; ++ks) {
#pragma unroll
            for (int np = 0; np < 4; ++np) {
                int nrow = np * 16 + ((grp >> 1) << 3) + (lane & 7);
                int kcol = ks * 16 + ((grp & 1) << 3);
                uint32_t bd = st + (uint32_t)(nrow * AT_S + kcol) * 2;
                uint32_t h4[4], l4[4];
                LDSM4(h4, bd);
                LDSM4(l4, bd + STG_KL);
                uint32_t bh0[2] = {h4[0], h4[1]}, bh1[2] = {h4[2], h4[3]};
                uint32_t bl0[2] = {l4[0], l4[1]}, bl1[2] = {l4[2], l4[3]};
                MMA16816(s[np*2],   qfh[ks], bh0);
                MMA16816(s[np*2],   qfh[ks], bl0);
                MMA16816(s[np*2],   qfl[ks], bh0);
                MMA16816(s[np*2+1], qfh[ks], bh1);
                MMA16816(s[np*2+1], qfh[ks], bl1);
                MMA16816(s[np*2+1], qfl[ks], bh1);
            }
        }

        // ---- mask ----
        const int c0 = 2 * ql;
#pragma unroll
        for (int nt = 0; nt < 8; ++nt) {
            if (msk[nt * 8 + c0]     == 0) { s[nt][0] = -1e9f; s[nt][2] = -1e9f; }
            if (msk[nt * 8 + c0 + 1] == 0) { s[nt][1] = -1e9f; s[nt][3] = -1e9f; }
        }

        // ---- online softmax ----
        float mxA = -1e30f, mxB = -1e30f;
#pragma unroll
        for (int nt = 0; nt < 8; ++nt) {
            mxA = fmaxf(mxA, fmaxf(s[nt][0], s[nt][1]));
            mxB = fmaxf(mxB, fmaxf(s[nt][2], s[nt][3]));
        }
#pragma unroll
        for (int o = 1; o <= 2; o <<= 1) {
            mxA = fmaxf(mxA, __shfl_xor_sync(0xffffffffu, mxA, o));
            mxB = fmaxf(mxB, __shfl_xor_sync(0xffffffffu, mxB, o));
        }
        const float mnA = fmaxf(m_i[0], mxA);
        const float mnB = fmaxf(m_i[1], mxB);
        const float sclA = fexp(m_i[0] - mnA);
        const float sclB = fexp(m_i[1] - mnB);
        m_i[0] = mnA; m_i[1] = mnB;

        float smA = 0.f, smB = 0.f;
#pragma unroll
        for (int nt = 0; nt < 8; ++nt) {
            s[nt][0] = fexp(s[nt][0] - mnA);
            s[nt][1] = fexp(s[nt][1] - mnA);
            s[nt][2] = fexp(s[nt][2] - mnB);
            s[nt][3] = fexp(s[nt][3] - mnB);
            smA += s[nt][0] + s[nt][1];
            smB += s[nt][2] + s[nt][3];
        }
#pragma unroll
        for (int o = 1; o <= 2; o <<= 1) {
            smA += __shfl_xor_sync(0xffffffffu, smA, o);
            smB += __shfl_xor_sync(0xffffffffu, smB, o);
        }
        l_i[0] = l_i[0] * sclA + smA;
        l_i[1] = l_i[1] * sclB + smB;
#pragma unroll
        for (int nt = 0; nt < 8; ++nt) {
            acc_o[nt][0] *= sclA; acc_o[nt][1] *= sclA;
            acc_o[nt][2] *= sclB; acc_o[nt][3] *= sclB;
        }

        // ---- ctx += P @ V  (trans-ldmatrix on row-major V; V hi+lo) ----
#pragma unroll
        for (int ks = 0; ks < 4; ++ks) {
            uint32_t aP[4];
            aP[0] = fpack2(s[2*ks  ][0], s[2*ks  ][1]);
            aP[1] = fpack2(s[2*ks  ][2], s[2*ks  ][3]);
            aP[2] = fpack2(s[2*ks+1][0], s[2*ks+1][1]);
            aP[3] = fpack2(s[2*ks+1][2], s[2*ks+1][3]);
#pragma unroll
            for (int np = 0; np < 4; ++np) {
                int key = ks * 16 + (((lane >> 3) & 1) << 3) + (lane & 7);
                int dkc = np * 16 + ((lane >> 4) << 3);
                uint32_t bd = st + STG_VH + (uint32_t)(key * AT_S + dkc) * 2;
                uint32_t v4[4], w4[4];
                LDSM4T(v4, bd);
                LDSM4T(w4, bd + (STG_VL - STG_VH));
                uint32_t bh0[2] = {v4[0], v4[1]}, bh1[2] = {v4[2], v4[3]};
                uint32_t bl0[2] = {w4[0], w4[1]}, bl1[2] = {w4[2], w4[3]};
                MMA16816(acc_o[np*2],   aP, bh0);
                MMA16816(acc_o[np*2],   aP, bl0);
                MMA16816(acc_o[np*2+1], aP, bh1);
                MMA16816(acc_o[np*2+1], aP, bl1);
            }
        }
    }

    // ---- epilogue ----
    const float invA = 1.f / l_i[0];
    const float invB = 1.f / l_i[1];
    const size_t obase = (size_t)(b * SEQ + q0 + mrow) * DIM + h * DK;
#pragma unroll
    for (int nt = 0; nt < 8; ++nt) {
        const int col = nt * 8 + 2 * ql;
        float2 vA = make_float2(acc_o[nt][0] * invA, acc_o[nt][1] * invA);
        float2 vB = make_float2(acc_o[nt][2] * invB, acc_o[nt][3] * invB);
        *(float2*)&O[obase + (size_t)quad * DIM + col]       = vA;
        *(float2*)&O[obase + (size_t)(quad + 8) * DIM + col] = vB;
    }
}

// ===========================================================================
// LayerNorm over last dim (1024). One block per row, 256 threads x float4.
// ===========================================================================
__global__ __launch_bounds__(256)
void layernorm_kernel(const float* __restrict__ in, const float* __restrict__ g,
                      const float* __restrict__ b, float* __restrict__ out)
{
    const int row = blockIdx.x;
    const int tid = threadIdx.x;
    const float4 v = ((const float4*)(in + (size_t)row * DIM))[tid];
    float s  = v.x + v.y + v.z + v.w;
    float sq = fmaf(v.x, v.x, fmaf(v.y, v.y, fmaf(v.z, v.z, v.w * v.w)));

#pragma unroll
    for (int o = 16; o >= 1; o >>= 1) {
        s  += __shfl_xor_sync(0xffffffffu, s,  o);
        sq += __shfl_xor_sync(0xffffffffu, sq, o);
    }
    __shared__ float ss[8], ssq[8];
    const int warp = tid >> 5, lane = tid & 31;
    if (lane == 0) { ss[warp] = s; ssq[warp] = sq; }
    __syncthreads();
    if (warp == 0) {
        float a = (lane < 8) ? ss[lane]  : 0.f;
        float q = (lane < 8) ? ssq[lane] : 0.f;
#pragma unroll
        for (int o = 4; o >= 1; o >>= 1) {
            a += __shfl_xor_sync(0xffffffffu, a, o);
            q += __shfl_xor_sync(0xffffffffu, q, o);
        }
        if (lane == 0) { ss[0] = a; ssq[0] = q; }
    }
    __syncthreads();
    const float mu   = ss[0]  * (1.f / DIM);
    const float var  = ssq[0] * (1.f / DIM) - mu * mu;
    const float rstd = rsqrtf(var + 1e-5f);

    const float4 gg = ((const float4*)g)[tid];
    const float4 bb = ((const float4*)b)[tid];
    float4 o;
    o.x = (v.x - mu) * rstd * gg.x + bb.x;
    o.y = (v.y - mu) * rstd * gg.y + bb.y;
    o.z = (v.z - mu) * rstd * gg.z + bb.z;
    o.w = (v.w - mu) * rstd * gg.w + bb.w;
    ((float4*)(out + (size_t)row * DIM))[tid] = o;
}

// ---------------------------------------------------------------------------
static void* sym_addr(const void* s)
{
    void* p = nullptr;
    cudaGetSymbolAddress(&p, s);
    return p;
}

extern "C" void kernel_launch(void* const* d_in, const int* in_sizes, int n_in,
                              void* d_out, int out_size)
{
    const float* x     = (const float*)d_in[0];
    const int*   mask  = (const int*)  d_in[1];
    const float* Wq    = (const float*)d_in[2];
    const float* Wk    = (const float*)d_in[3];
    const float* Wv    = (const float*)d_in[4];
    const float* Wo    = (const float*)d_in[5];
    const float* W1    = (const float*)d_in[6];
    const float* b1    = (const float*)d_in[7];
    const float* W2    = (const float*)d_in[8];
    const float* b2    = (const float*)d_in[9];
    const float* ln1_g = (const float*)d_in[10];
    const float* ln1_b = (const float*)d_in[11];
    const float* ln2_g = (const float*)d_in[12];
    const float* ln2_b = (const float*)d_in[13];
    float* out = (float*)d_out;

    float* Cx  = (float*)sym_addr(g_ctx);
    float* T1  = (float*)sym_addr(g_t1);
    float* Hb  = (float*)sym_addr(g_h);
    float* Ff  = (float*)sym_addr(g_ff);
    __nv_bfloat16* qh = (__nv_bfloat16*)sym_addr(g_Qh);
    __nv_bfloat16* qlp= (__nv_bfloat16*)sym_addr(g_Ql);
    __nv_bfloat16* kh = (__nv_bfloat16*)sym_addr(g_Kh);
    __nv_bfloat16* kl = (__nv_bfloat16*)sym_addr(g_Kl);
    __nv_bfloat16* vh = (__nv_bfloat16*)sym_addr(g_Vh);
    __nv_bfloat16* vl = (__nv_bfloat16*)sym_addr(g_Vl);
    __nv_bfloat16* wh = (__nv_bfloat16*)sym_addr(g_wh);
    __nv_bfloat16* wl = (__nv_bfloat16*)sym_addr(g_wl);

    static bool attr_set = false;
    if (!attr_set) {
        cudaFuncSetAttribute(attn_mma,
            cudaFuncAttributeMaxDynamicSharedMemorySize, AT_SMEM);
        cudaFuncSetAttribute(hgemm<false, false, false, true>,
            cudaFuncAttributeMaxDynamicSharedMemorySize, HG_SMEM);
        cudaFuncSetAttribute(hgemm<false, false, true, false>,
            cudaFuncAttributeMaxDynamicSharedMemorySize, HG_SMEM);
        cudaFuncSetAttribute(hgemm<true, true, false, false>,
            cudaFuncAttributeMaxDynamicSharedMemorySize, HG_SMEM);
        cudaFuncSetAttribute(hgemm<true, false, true, false>,
            cudaFuncAttributeMaxDynamicSharedMemorySize, HG_SMEM);
        attr_set = true;
    }

    const dim3 blk(256);

    // ---- weight pre-split ----
    wsplit<<<dim3(DIM / 32, DIM / 32), blk>>>(Wq, DIM, DIM, wh + WOFF_Q, wl + WOFF_Q);
    wsplit<<<dim3(DIM / 32, DIM / 32), blk>>>(Wk, DIM, DIM, wh + WOFF_K, wl + WOFF_K);
    wsplit<<<dim3(DIM / 32, DIM / 32), blk>>>(Wv, DIM, DIM, wh + WOFF_V, wl + WOFF_V);
    wsplit<<<dim3(DIM / 32, DIM / 32), blk>>>(Wo, DIM, DIM, wh + WOFF_O, wl + WOFF_O);
    wsplit<<<dim3(DFF / 32, DIM / 32), blk>>>(W1, DIM, DFF, wh + WOFF_W1, wl + WOFF_W1);
    wsplit<<<dim3(DIM / 32, DFF / 32), blk>>>(W2, DFF, DIM, wh + WOFF_W2, wl + WOFF_W2);

    const dim3 gD  (DIM / 64, TOK / 128);    // (16, 64)
    const dim3 gDFF(DFF / 64, TOK / 128);    // (64, 64)

    // projections -> split-bf16 outputs (1/sqrt(dk)=0.125 folded into Q)
    hgemm<false, false, false, true><<<gD, blk, HG_SMEM>>>(
        x, wh + WOFF_Q, wl + WOFF_Q, nullptr, nullptr, nullptr, qh, qlp, DIM, DIM, 0.125f);
    hgemm<false, false, false, true><<<gD, blk, HG_SMEM>>>(
        x, wh + WOFF_K, wl + WOFF_K, nullptr, nullptr, nullptr, kh, kl, DIM, DIM, 1.0f);
    hgemm<false, false, false, true><<<gD, blk, HG_SMEM>>>(
        x, wh + WOFF_V, wl + WOFF_V, nullptr, nullptr, nullptr, vh, vl, DIM, DIM, 1.0f);

    // attention (tensorized, pipelined)
    attn_mma<<<dim3(SEQ / 128, NB * NH), blk, AT_SMEM>>>(
        qh, qlp, kh, kl, vh, vl, mask, Cx);

    // output projection + residual, LN1
    hgemm<false, false, true, false><<<gD, blk, HG_SMEM>>>(
        Cx, wh + WOFF_O, wl + WOFF_O, nullptr, x, T1, nullptr, nullptr, DIM, DIM, 1.0f);
    layernorm_kernel<<<TOK, blk>>>(T1, ln1_g, ln1_b, Hb);

    // FFN + residual, LN2
    hgemm<true, true, false, false><<<gDFF, blk, HG_SMEM>>>(
        Hb, wh + WOFF_W1, wl + WOFF_W1, b1, nullptr, Ff, nullptr, nullptr, DFF, DIM, 1.0f);
    hgemm<true, false, true, false><<<gD, blk, HG_SMEM>>>(
        Ff, wh + WOFF_W2, wl + WOFF_W2, b2, Hb, T1, nullptr, nullptr, DIM, DFF, 1.0f);
    layernorm_kernel<<<TOK, blk>>>(T1, ln2_g, ln2_b, out);
}

// round 17
// speedup vs baseline: 2.8708x; 1.0837x over previous
#include <cuda_runtime.h>
#include <cuda_bf16.h>
#include <cuda_fp16.h>
#include <cstdint>

// ---------------------------------------------------------------------------
// EncoderLayer: B=4 S=2048 D=1024 H=16 dk=64 Dff=4096, fp32 in/out.
// GEMMs: mma.sync bf16 split-bf16 (3-term) error compensation.
// Attention v3: FULL fp16 (single-term Q,K,V; 11-bit mantissa), cp.async
// double-buffered K/V, ldmatrix(.trans), register-resident Q fragments,
// FMA-pipe exp polynomial. 2.5x fewer attention MMAs than v2.
// ---------------------------------------------------------------------------

constexpr int NB  = 4;
constexpr int SEQ = 2048;
constexpr int DIM = 1024;
constexpr int NH  = 16;
constexpr int DK  = 64;
constexpr int DFF = 4096;
constexpr int TOK = NB * SEQ;          // 8192

// scratch (device globals: allocation-free per harness rules)
__device__ float g_ctx[TOK * DIM];
__device__ float g_t1 [TOK * DIM];
__device__ float g_h  [TOK * DIM];
__device__ float g_ff [(size_t)TOK * DFF];
__device__ __half g_Qf[TOK * DIM], g_Kf[TOK * DIM], g_Vf[TOK * DIM];
// pre-split weights, [N][K] layout, bf16 hi/lo.
constexpr size_t WOFF_Q  = 0;
constexpr size_t WOFF_K  = 1ull << 20;
constexpr size_t WOFF_V  = 2ull << 20;
constexpr size_t WOFF_O  = 3ull << 20;
constexpr size_t WOFF_W1 = 4ull << 20;
constexpr size_t WOFF_W2 = 8ull << 20;
__device__ __nv_bfloat16 g_wh[12ull << 20];
__device__ __nv_bfloat16 g_wl[12ull << 20];

// ===========================================================================
// helpers
// ===========================================================================
__device__ __forceinline__ uint32_t smem_u32(const void* p) {
    uint32_t a;
    asm("{ .reg .u64 t; cvta.to.shared.u64 t, %1; cvt.u32.u64 %0, t; }"
        : "=r"(a) : "l"(p));
    return a;
}

#define LDSM4(r, addr) \
    asm volatile("ldmatrix.sync.aligned.m8n8.x4.shared.b16 {%0,%1,%2,%3}, [%4];" \
        : "=r"((r)[0]), "=r"((r)[1]), "=r"((r)[2]), "=r"((r)[3]) : "r"(addr))

#define LDSM4T(r, addr) \
    asm volatile("ldmatrix.sync.aligned.m8n8.x4.trans.shared.b16 {%0,%1,%2,%3}, [%4];" \
        : "=r"((r)[0]), "=r"((r)[1]), "=r"((r)[2]), "=r"((r)[3]) : "r"(addr))

// bf16 MMA (GEMM path)
#define MMA16816(d, a, b) \
    asm volatile("mma.sync.aligned.m16n8k16.row.col.f32.bf16.bf16.f32 " \
        "{%0,%1,%2,%3}, {%4,%5,%6,%7}, {%8,%9}, {%0,%1,%2,%3};" \
        : "+f"((d)[0]), "+f"((d)[1]), "+f"((d)[2]), "+f"((d)[3]) \
        : "r"((a)[0]), "r"((a)[1]), "r"((a)[2]), "r"((a)[3]), \
          "r"((b)[0]), "r"((b)[1]))

// fp16 MMA (attention path)
#define MMAH16816(d, a, b) \
    asm volatile("mma.sync.aligned.m16n8k16.row.col.f32.f16.f16.f32 " \
        "{%0,%1,%2,%3}, {%4,%5,%6,%7}, {%8,%9}, {%0,%1,%2,%3};" \
        : "+f"((d)[0]), "+f"((d)[1]), "+f"((d)[2]), "+f"((d)[3]) \
        : "r"((a)[0]), "r"((a)[1]), "r"((a)[2]), "r"((a)[3]), \
          "r"((b)[0]), "r"((b)[1]))

#define CPASYNC16(dst, src) \
    asm volatile("cp.async.cg.shared.global [%0], [%1], 16;" \
                 :: "r"((uint32_t)(dst)), "l"(src) : "memory")
#define CPASYNC_COMMIT() asm volatile("cp.async.commit_group;" ::: "memory")
#define CPASYNC_WAIT0()  asm volatile("cp.async.wait_group 0;" ::: "memory")

__device__ __forceinline__ uint32_t bfpack(__nv_bfloat16 a, __nv_bfloat16 b) {
    __nv_bfloat162 t; t.x = a; t.y = b;
    return *reinterpret_cast<uint32_t*>(&t);
}
__device__ __forceinline__ uint32_t hpack2(float a, float b) {
    __half2 t = __floats2half2_rn(a, b);
    return *reinterpret_cast<uint32_t*>(&t);
}
__device__ __forceinline__ void bsplit(float v, __nv_bfloat16& h, __nv_bfloat16& l) {
    h = __float2bfloat16(v);
    l = __float2bfloat16(v - __bfloat162float(h));
}

// fast exp on the FMA pipe
__device__ __forceinline__ float fexp(float x) {
    x = fmaxf(x, -87.f);
    float t = fmaf(x, 1.4426950408889634f, 12582912.f);
    int   n = __float_as_int(t) - 0x4B400000;
    float f = fmaf(x, 1.4426950408889634f, -(t - 12582912.f));
    float p =             1.3333558146e-3f;
    p = fmaf(p, f, 9.6181291076e-3f);
    p = fmaf(p, f, 5.5504108664e-2f);
    p = fmaf(p, f, 2.4022650696e-1f);
    p = fmaf(p, f, 6.9314718056e-1f);
    p = fmaf(p, f, 1.0f);
    return __int_as_float(__float_as_int(p) + (n << 23));
}

// ===========================================================================
// Weight pre-pass: W[K,N] fp32 -> hi/lo bf16 in [N,K] layout (transposed).
// ===========================================================================
__global__ __launch_bounds__(256)
void wsplit(const float* __restrict__ W, int K, int N,
            __nv_bfloat16* __restrict__ oh, __nv_bfloat16* __restrict__ ol)
{
    __shared__ float t[32][33];
    const int k0 = blockIdx.y * 32, n0 = blockIdx.x * 32;
    const int tx = threadIdx.x & 31, ty = threadIdx.x >> 5;
#pragma unroll
    for (int j = ty; j < 32; j += 8)
        t[j][tx] = W[(size_t)(k0 + j) * N + n0 + tx];
    __syncthreads();
#pragma unroll
    for (int j = ty; j < 32; j += 8) {
        float v = t[tx][j];
        __nv_bfloat16 h, l; bsplit(v, h, l);
        oh[(size_t)(n0 + j) * K + k0 + tx] = h;
        ol[(size_t)(n0 + j) * K + k0 + tx] = l;
    }
}

// ===========================================================================
// HMMA GEMM (R16-passing core; H16OUT epilogue writes single fp16 buffer).
// ===========================================================================
constexpr int HG_STAGE  = 30720;
constexpr int HG_SMEM   = 2 * HG_STAGE;
constexpr int OFF_AL    = 10240;
constexpr int OFF_BH    = 20480;
constexpr int OFF_BL    = 25600;

template<bool BIAS, bool RELU, bool RES, bool H16OUT>
__global__ __launch_bounds__(256)
void hgemm(const float* __restrict__ A,
           const __nv_bfloat16* __restrict__ Bhg,
           const __nv_bfloat16* __restrict__ Blg,
           const float* __restrict__ bias, const float* __restrict__ res,
           float* __restrict__ C, __half* __restrict__ Cf,
           int N, int K, float alpha)
{
    extern __shared__ char smem[];
    const uint32_t sbase = smem_u32(smem);

    const int tid    = threadIdx.x;
    const int lane   = tid & 31;
    const int wid    = tid >> 5;
    const int warp_m = wid & 3;
    const int warp_n = wid >> 2;
    const int mbase  = warp_m * 32;
    const int nbase  = warp_n * 32;
    const int row0   = blockIdx.y * 128;
    const int col0   = blockIdx.x * 64;

    const int nk = K >> 5;

    float acc[2][4][4];
#pragma unroll
    for (int mt = 0; mt < 2; ++mt)
#pragma unroll
        for (int nt = 0; nt < 4; ++nt)
#pragma unroll
            for (int i = 0; i < 4; ++i) acc[mt][nt][i] = 0.f;

    float4 pa[4];
    uint2  pbh[2], pbl[2];
    const float* Ab = A + (size_t)row0 * K;

#pragma unroll
    for (int it = 0; it < 4; ++it) {
        int idx = it * 256 + tid, r = idx >> 3, c4 = idx & 7;
        pa[it] = *(const float4*)&Ab[(size_t)r * K + c4 * 4];
    }
#pragma unroll
    for (int it = 0; it < 2; ++it) {
        int idx = it * 256 + tid, r = idx >> 3, c4 = idx & 7;
        pbh[it] = *(const uint2*)&Bhg[(size_t)(col0 + r) * K + c4 * 4];
        pbl[it] = *(const uint2*)&Blg[(size_t)(col0 + r) * K + c4 * 4];
    }
    {
        char* st = smem;
#pragma unroll
        for (int it = 0; it < 4; ++it) {
            int idx = it * 256 + tid, r = idx >> 3, c4 = idx & 7;
            __nv_bfloat16 h0,h1,h2,h3,l0,l1,l2,l3;
            bsplit(pa[it].x,h0,l0); bsplit(pa[it].y,h1,l1);
            bsplit(pa[it].z,h2,l2); bsplit(pa[it].w,h3,l3);
            uint32_t off = (uint32_t)(r * 40 + c4 * 4) * 2;
            uint2 hp; hp.x = bfpack(h0,h1); hp.y = bfpack(h2,h3);
            uint2 lp; lp.x = bfpack(l0,l1); lp.y = bfpack(l2,l3);
            *(uint2*)(st + off)           = hp;
            *(uint2*)(st + OFF_AL + off)  = lp;
        }
#pragma unroll
        for (int it = 0; it < 2; ++it) {
            int idx = it * 256 + tid, r = idx >> 3, c4 = idx & 7;
            uint32_t off = (uint32_t)(r * 40 + c4 * 4) * 2;
            *(uint2*)(st + OFF_BH + off) = pbh[it];
            *(uint2*)(st + OFF_BL + off) = pbl[it];
        }
    }
    __syncthreads();

    for (int kb = 0; kb < nk; ++kb) {
        if (kb + 1 < nk) {
            const float* Ap = Ab + ((kb + 1) << 5);
#pragma unroll
            for (int it = 0; it < 4; ++it) {
                int idx = it * 256 + tid, r = idx >> 3, c4 = idx & 7;
                pa[it] = *(const float4*)&Ap[(size_t)r * K + c4 * 4];
            }
            const size_t bofs = ((size_t)(kb + 1) << 5);
#pragma unroll
            for (int it = 0; it < 2; ++it) {
                int idx = it * 256 + tid, r = idx >> 3, c4 = idx & 7;
                pbh[it] = *(const uint2*)&Bhg[(size_t)(col0 + r) * K + bofs + c4 * 4];
                pbl[it] = *(const uint2*)&Blg[(size_t)(col0 + r) * K + bofs + c4 * 4];
            }
        }

        const uint32_t sb = sbase + (uint32_t)(kb & 1) * HG_STAGE;
#pragma unroll
        for (int ks = 0; ks < 2; ++ks) {
            uint32_t ah[2][4], al[2][4], bh[4][2], bl[4][2];
#pragma unroll
            for (int mt = 0; mt < 2; ++mt) {
                int row = mbase + mt * 16 + (lane & 15);
                int col = ks * 16 + ((lane >> 4) << 3);
                uint32_t ad = sb + (uint32_t)(row * 40 + col) * 2;
                LDSM4(ah[mt], ad);
                LDSM4(al[mt], ad + OFF_AL);
            }
#pragma unroll
            for (int np = 0; np < 2; ++np) {
                int grp  = lane >> 3;
                int nrow = nbase + np * 16 + ((grp >> 1) << 3) + (lane & 7);
                int kcol = ks * 16 + ((grp & 1) << 3);
                uint32_t bd = sb + OFF_BH + (uint32_t)(nrow * 40 + kcol) * 2;
                uint32_t q[4];
                LDSM4(q, bd);
                bh[np*2][0] = q[0]; bh[np*2][1] = q[1];
                bh[np*2+1][0] = q[2]; bh[np*2+1][1] = q[3];
                LDSM4(q, bd + (OFF_BL - OFF_BH));
                bl[np*2][0] = q[0]; bl[np*2][1] = q[1];
                bl[np*2+1][0] = q[2]; bl[np*2+1][1] = q[3];
            }
#pragma unroll
            for (int mt = 0; mt < 2; ++mt)
#pragma unroll
                for (int nt = 0; nt < 4; ++nt) {
                    MMA16816(acc[mt][nt], ah[mt], bh[nt]);
                    MMA16816(acc[mt][nt], ah[mt], bl[nt]);
                    MMA16816(acc[mt][nt], al[mt], bh[nt]);
                }
        }

        if (kb + 1 < nk) {
            char* st = smem + ((kb + 1) & 1) * HG_STAGE;
#pragma unroll
            for (int it = 0; it < 4; ++it) {
                int idx = it * 256 + tid, r = idx >> 3, c4 = idx & 7;
                __nv_bfloat16 h0,h1,h2,h3,l0,l1,l2,l3;
                bsplit(pa[it].x,h0,l0); bsplit(pa[it].y,h1,l1);
                bsplit(pa[it].z,h2,l2); bsplit(pa[it].w,h3,l3);
                uint32_t off = (uint32_t)(r * 40 + c4 * 4) * 2;
                uint2 hp; hp.x = bfpack(h0,h1); hp.y = bfpack(h2,h3);
                uint2 lp; lp.x = bfpack(l0,l1); lp.y = bfpack(l2,l3);
                *(uint2*)(st + off)          = hp;
                *(uint2*)(st + OFF_AL + off) = lp;
            }
#pragma unroll
            for (int it = 0; it < 2; ++it) {
                int idx = it * 256 + tid, r = idx >> 3, c4 = idx & 7;
                uint32_t off = (uint32_t)(r * 40 + c4 * 4) * 2;
                *(uint2*)(st + OFF_BH + off) = pbh[it];
                *(uint2*)(st + OFF_BL + off) = pbl[it];
            }
        }
        __syncthreads();
    }

    const int quad  = lane >> 2;
    const int qlane = lane & 3;
#pragma unroll
    for (int mt = 0; mt < 2; ++mt) {
#pragma unroll
        for (int nt = 0; nt < 4; ++nt) {
            const int cg = col0 + nbase + nt * 8 + (qlane << 1);
#pragma unroll
            for (int h = 0; h < 2; ++h) {
                const int rg = row0 + mbase + mt * 16 + quad + h * 8;
                float2 v;
                v.x = acc[mt][nt][h * 2 + 0] * alpha;
                v.y = acc[mt][nt][h * 2 + 1] * alpha;
                if (BIAS) {
                    float2 bb = *(const float2*)&bias[cg];
                    v.x += bb.x; v.y += bb.y;
                }
                if (RES) {
                    float2 rr = *(const float2*)&res[(size_t)rg * N + cg];
                    v.x += rr.x; v.y += rr.y;
                }
                if (RELU) { v.x = fmaxf(v.x, 0.f); v.y = fmaxf(v.y, 0.f); }
                if (H16OUT) {
                    *(uint32_t*)&Cf[(size_t)rg * N + cg] = hpack2(v.x, v.y);
                } else {
                    *(float2*)&C[(size_t)rg * N + cg] = v;
                }
            }
        }
    }
}

// ===========================================================================
// Tensorized flash attention v3 — full fp16, single-term.
// Grid (SEQ/128, NB*NH), 256 thr = 8 warps x 16 query rows. Key tile = 64.
// Stage layout (bytes): K 0, V 9216, MSK 18432; 18688/stage, 2 stages.
// ===========================================================================
constexpr int AT_S    = 72;             // row stride in halves (144 B)
constexpr int STG_V   = 9216;
constexpr int STG_MSK = 18432;
constexpr int STG_B   = 18688;
constexpr int AT_SMEM = 2 * STG_B;      // 37376

__global__ __launch_bounds__(256, 2)
void attn_mma(const __half* __restrict__ Qf, const __half* __restrict__ Kf,
              const __half* __restrict__ Vf,
              const int* __restrict__ mask, float* __restrict__ O)
{
    extern __shared__ char smraw[];
    const uint32_t sbase = smem_u32(smraw);

    const int tid  = threadIdx.x;
    const int lane = tid & 31;
    const int wid  = tid >> 5;
    const int quad = lane >> 2;
    const int ql   = lane & 3;
    const int grp  = lane >> 3;
    const int b    = blockIdx.y >> 4;
    const int h    = blockIdx.y & 15;
    const int q0   = blockIdx.x * 128;
    const int mrow = wid * 16;
    const int ch   = tid & 7;

    const size_t qbase = (size_t)(b * SEQ + q0) * DIM + h * DK;
    const size_t kvb0  = (size_t)(b * SEQ) * DIM + h * DK;

    // ---- stage Q (fp16) into buffer region, extract fragments ----
    {
        __half* sq = (__half*)smraw;
#pragma unroll
        for (int it = 0; it < 4; ++it) {
            int r = (it * 256 + tid) >> 3;
            *(uint4*)&sq[r * AT_S + ch * 8] =
                *(const uint4*)&Qf[qbase + (size_t)r * DIM + ch * 8];
        }
    }
    __syncthreads();
    uint32_t qf[4][4];
    {
        int row = mrow + (lane & 15);
        int col = (lane >> 4) << 3;
#pragma unroll
        for (int ks = 0; ks < 4; ++ks) {
            uint32_t ad = sbase + (uint32_t)(row * AT_S + ks * 16 + col) * 2;
            LDSM4(qf[ks], ad);
        }
    }
    __syncthreads();   // Q fragments extracted; buffer reusable

    // ---- issue tile 0 ----
    {
        const uint32_t stg = sbase;
#pragma unroll
        for (int it = 0; it < 2; ++it) {
            int r = (it * 256 + tid) >> 3;
            uint32_t d = (uint32_t)(r * AT_S + ch * 8) * 2;
            const size_t g = kvb0 + (size_t)r * DIM + ch * 8;
            CPASYNC16(stg + d,          &Kf[g]);
            CPASYNC16(stg + STG_V + d,  &Vf[g]);
        }
        if (tid < 16) CPASYNC16(stg + STG_MSK + tid * 16, &mask[b * SEQ + tid * 4]);
        CPASYNC_COMMIT();
    }

    float m_i[2] = {-1e30f, -1e30f};
    float l_i[2] = {0.f, 0.f};
    float acc_o[8][4];
#pragma unroll
    for (int nt = 0; nt < 8; ++nt)
#pragma unroll
        for (int i = 0; i < 4; ++i) acc_o[nt][i] = 0.f;

    const int NT = SEQ / 64;   // 32 tiles
    for (int t = 0; t < NT; ++t) {
        CPASYNC_WAIT0();
        __syncthreads();

        // prefetch tile t+1
        if (t + 1 < NT) {
            const size_t kbase = kvb0 + (size_t)((t + 1) * 64) * DIM;
            const uint32_t stg = sbase + ((t + 1) & 1) * STG_B;
#pragma unroll
            for (int it = 0; it < 2; ++it) {
                int r = (it * 256 + tid) >> 3;
                uint32_t d = (uint32_t)(r * AT_S + ch * 8) * 2;
                const size_t g = kbase + (size_t)r * DIM + ch * 8;
                CPASYNC16(stg + d,         &Kf[g]);
                CPASYNC16(stg + STG_V + d, &Vf[g]);
            }
            if (tid < 16)
                CPASYNC16(stg + STG_MSK + tid * 16,
                          &mask[b * SEQ + (t + 1) * 64 + tid * 4]);
            CPASYNC_COMMIT();
        }

        const uint32_t st = sbase + (t & 1) * STG_B;
        const int* msk = (const int*)(smraw + (t & 1) * STG_B + STG_MSK);

        // ---- S = Q @ K^T (single fp16 term) ----
        float s[8][4];
#pragma unroll
        for (int nt = 0; nt < 8; ++nt)
#pragma unroll
            for (int i = 0; i < 4; ++i) s[nt][i] = 0.f;

#pragma unroll
        for (int ks = 0; ks < 4; ++ks) {
#pragma unroll
            for (int np = 0; np < 4; ++np) {
                int nrow = np * 16 + ((grp >> 1) << 3) + (lane & 7);
                int kcol = ks * 16 + ((grp & 1) << 3);
                uint32_t bd = st + (uint32_t)(nrow * AT_S + kcol) * 2;
                uint32_t k4[4];
                LDSM4(k4, bd);
                uint32_t b0[2] = {k4[0], k4[1]}, b1[2] = {k4[2], k4[3]};
                MMAH16816(s[np*2],   qf[ks], b0);
                MMAH16816(s[np*2+1], qf[ks], b1);
            }
        }

        // ---- mask ----
        const int c0 = 2 * ql;
#pragma unroll
        for (int nt = 0; nt < 8; ++nt) {
            if (msk[nt * 8 + c0]     == 0) { s[nt][0] = -1e9f; s[nt][2] = -1e9f; }
            if (msk[nt * 8 + c0 + 1] == 0) { s[nt][1] = -1e9f; s[nt][3] = -1e9f; }
        }

        // ---- online softmax ----
        float mxA = -1e30f, mxB = -1e30f;
#pragma unroll
        for (int nt = 0; nt < 8; ++nt) {
            mxA = fmaxf(mxA, fmaxf(s[nt][0], s[nt][1]));
            mxB = fmaxf(mxB, fmaxf(s[nt][2], s[nt][3]));
        }
#pragma unroll
        for (int o = 1; o <= 2; o <<= 1) {
            mxA = fmaxf(mxA, __shfl_xor_sync(0xffffffffu, mxA, o));
            mxB = fmaxf(mxB, __shfl_xor_sync(0xffffffffu, mxB, o));
        }
        const float mnA = fmaxf(m_i[0], mxA);
        const float mnB = fmaxf(m_i[1], mxB);
        const float sclA = fexp(m_i[0] - mnA);
        const float sclB = fexp(m_i[1] - mnB);
        m_i[0] = mnA; m_i[1] = mnB;

        float smA = 0.f, smB = 0.f;
#pragma unroll
        for (int nt = 0; nt < 8; ++nt) {
            s[nt][0] = fexp(s[nt][0] - mnA);
            s[nt][1] = fexp(s[nt][1] - mnA);
            s[nt][2] = fexp(s[nt][2] - mnB);
            s[nt][3] = fexp(s[nt][3] - mnB);
            smA += s[nt][0] + s[nt][1];
            smB += s[nt][2] + s[nt][3];
        }
#pragma unroll
        for (int o = 1; o <= 2; o <<= 1) {
            smA += __shfl_xor_sync(0xffffffffu, smA, o);
            smB += __shfl_xor_sync(0xffffffffu, smB, o);
        }
        l_i[0] = l_i[0] * sclA + smA;
        l_i[1] = l_i[1] * sclB + smB;
#pragma unroll
        for (int nt = 0; nt < 8; ++nt) {
            acc_o[nt][0] *= sclA; acc_o[nt][1] *= sclA;
            acc_o[nt][2] *= sclB; acc_o[nt][3] *= sclB;
        }

        // ---- ctx += P @ V  (fp16 P, fp16 V, trans-ldmatrix) ----
#pragma unroll
        for (int ks = 0; ks < 4; ++ks) {
            uint32_t aP[4];
            aP[0] = hpack2(s[2*ks  ][0], s[2*ks  ][1]);
            aP[1] = hpack2(s[2*ks  ][2], s[2*ks  ][3]);
            aP[2] = hpack2(s[2*ks+1][0], s[2*ks+1][1]);
            aP[3] = hpack2(s[2*ks+1][2], s[2*ks+1][3]);
#pragma unroll
            for (int np = 0; np < 4; ++np) {
                int key = ks * 16 + (((lane >> 3) & 1) << 3) + (lane & 7);
                int dkc = np * 16 + ((lane >> 4) << 3);
                uint32_t bd = st + STG_V + (uint32_t)(key * AT_S + dkc) * 2;
                uint32_t v4[4];
                LDSM4T(v4, bd);
                uint32_t b0[2] = {v4[0], v4[1]}, b1[2] = {v4[2], v4[3]};
                MMAH16816(acc_o[np*2],   aP, b0);
                MMAH16816(acc_o[np*2+1], aP, b1);
            }
        }
    }

    // ---- epilogue ----
    const float invA = 1.f / l_i[0];
    const float invB = 1.f / l_i[1];
    const size_t obase = (size_t)(b * SEQ + q0 + mrow) * DIM + h * DK;
#pragma unroll
    for (int nt = 0; nt < 8; ++nt) {
        const int col = nt * 8 + 2 * ql;
        float2 vA = make_float2(acc_o[nt][0] * invA, acc_o[nt][1] * invA);
        float2 vB = make_float2(acc_o[nt][2] * invB, acc_o[nt][3] * invB);
        *(float2*)&O[obase + (size_t)quad * DIM + col]       = vA;
        *(float2*)&O[obase + (size_t)(quad + 8) * DIM + col] = vB;
    }
}

// ===========================================================================
// LayerNorm over last dim (1024). One block per row, 256 threads x float4.
// ===========================================================================
__global__ __launch_bounds__(256)
void layernorm_kernel(const float* __restrict__ in, const float* __restrict__ g,
                      const float* __restrict__ b, float* __restrict__ out)
{
    const int row = blockIdx.x;
    const int tid = threadIdx.x;
    const float4 v = ((const float4*)(in + (size_t)row * DIM))[tid];
    float s  = v.x + v.y + v.z + v.w;
    float sq = fmaf(v.x, v.x, fmaf(v.y, v.y, fmaf(v.z, v.z, v.w * v.w)));

#pragma unroll
    for (int o = 16; o >= 1; o >>= 1) {
        s  += __shfl_xor_sync(0xffffffffu, s,  o);
        sq += __shfl_xor_sync(0xffffffffu, sq, o);
    }
    __shared__ float ss[8], ssq[8];
    const int warp = tid >> 5, lane = tid & 31;
    if (lane == 0) { ss[warp] = s; ssq[warp] = sq; }
    __syncthreads();
    if (warp == 0) {
        float a = (lane < 8) ? ss[lane]  : 0.f;
        float q = (lane < 8) ? ssq[lane] : 0.f;
#pragma unroll
        for (int o = 4; o >= 1; o >>= 1) {
            a += __shfl_xor_sync(0xffffffffu, a, o);
            q += __shfl_xor_sync(0xffffffffu, q, o);
        }
        if (lane == 0) { ss[0] = a; ssq[0] = q; }
    }
    __syncthreads();
    const float mu   = ss[0]  * (1.f / DIM);
    const float var  = ssq[0] * (1.f / DIM) - mu * mu;
    const float rstd = rsqrtf(var + 1e-5f);

    const float4 gg = ((const float4*)g)[tid];
    const float4 bb = ((const float4*)b)[tid];
    float4 o;
    o.x = (v.x - mu) * rstd * gg.x + bb.x;
    o.y = (v.y - mu) * rstd * gg.y + bb.y;
    o.z = (v.z - mu) * rstd * gg.z + bb.z;
    o.w = (v.w - mu) * rstd * gg.w + bb.w;
    ((float4*)(out + (size_t)row * DIM))[tid] = o;
}

// ---------------------------------------------------------------------------
static void* sym_addr(const void* s)
{
    void* p = nullptr;
    cudaGetSymbolAddress(&p, s);
    return p;
}

extern "C" void kernel_launch(void* const* d_in, const int* in_sizes, int n_in,
                              void* d_out, int out_size)
{
    const float* x     = (const float*)d_in[0];
    const int*   mask  = (const int*)  d_in[1];
    const float* Wq    = (const float*)d_in[2];
    const float* Wk    = (const float*)d_in[3];
    const float* Wv    = (const float*)d_in[4];
    const float* Wo    = (const float*)d_in[5];
    const float* W1    = (const float*)d_in[6];
    const float* b1    = (const float*)d_in[7];
    const float* W2    = (const float*)d_in[8];
    const float* b2    = (const float*)d_in[9];
    const float* ln1_g = (const float*)d_in[10];
    const float* ln1_b = (const float*)d_in[11];
    const float* ln2_g = (const float*)d_in[12];
    const float* ln2_b = (const float*)d_in[13];
    float* out = (float*)d_out;

    float* Cx  = (float*)sym_addr(g_ctx);
    float* T1  = (float*)sym_addr(g_t1);
    float* Hb  = (float*)sym_addr(g_h);
    float* Ff  = (float*)sym_addr(g_ff);
    __half* qf = (__half*)sym_addr(g_Qf);
    __half* kf = (__half*)sym_addr(g_Kf);
    __half* vf = (__half*)sym_addr(g_Vf);
    __nv_bfloat16* wh = (__nv_bfloat16*)sym_addr(g_wh);
    __nv_bfloat16* wl = (__nv_bfloat16*)sym_addr(g_wl);

    static bool attr_set = false;
    if (!attr_set) {
        cudaFuncSetAttribute(attn_mma,
            cudaFuncAttributeMaxDynamicSharedMemorySize, AT_SMEM);
        cudaFuncSetAttribute(hgemm<false, false, false, true>,
            cudaFuncAttributeMaxDynamicSharedMemorySize, HG_SMEM);
        cudaFuncSetAttribute(hgemm<false, false, true, false>,
            cudaFuncAttributeMaxDynamicSharedMemorySize, HG_SMEM);
        cudaFuncSetAttribute(hgemm<true, true, false, false>,
            cudaFuncAttributeMaxDynamicSharedMemorySize, HG_SMEM);
        cudaFuncSetAttribute(hgemm<true, false, true, false>,
            cudaFuncAttributeMaxDynamicSharedMemorySize, HG_SMEM);
        attr_set = true;
    }

    const dim3 blk(256);

    // ---- weight pre-split ----
    wsplit<<<dim3(DIM / 32, DIM / 32), blk>>>(Wq, DIM, DIM, wh + WOFF_Q, wl + WOFF_Q);
    wsplit<<<dim3(DIM / 32, DIM / 32), blk>>>(Wk, DIM, DIM, wh + WOFF_K, wl + WOFF_K);
    wsplit<<<dim3(DIM / 32, DIM / 32), blk>>>(Wv, DIM, DIM, wh + WOFF_V, wl + WOFF_V);
    wsplit<<<dim3(DIM / 32, DIM / 32), blk>>>(Wo, DIM, DIM, wh + WOFF_O, wl + WOFF_O);
    wsplit<<<dim3(DFF / 32, DIM / 32), blk>>>(W1, DIM, DFF, wh + WOFF_W1, wl + WOFF_W1);
    wsplit<<<dim3(DIM / 32, DFF / 32), blk>>>(W2, DFF, DIM, wh + WOFF_W2, wl + WOFF_W2);

    const dim3 gD  (DIM / 64, TOK / 128);    // (16, 64)
    const dim3 gDFF(DFF / 64, TOK / 128);    // (64, 64)

    // projections -> fp16 outputs (1/sqrt(dk)=0.125 folded into Q)
    hgemm<false, false, false, true><<<gD, blk, HG_SMEM>>>(
        x, wh + WOFF_Q, wl + WOFF_Q, nullptr, nullptr, nullptr, qf, DIM, DIM, 0.125f);
    hgemm<false, false, false, true><<<gD, blk, HG_SMEM>>>(
        x, wh + WOFF_K, wl + WOFF_K, nullptr, nullptr, nullptr, kf, DIM, DIM, 1.0f);
    hgemm<false, false, false, true><<<gD, blk, HG_SMEM>>>(
        x, wh + WOFF_V, wl + WOFF_V, nullptr, nullptr, nullptr, vf, DIM, DIM, 1.0f);

    // attention (fp16, pipelined)
    attn_mma<<<dim3(SEQ / 128, NB * NH), blk, AT_SMEM>>>(qf, kf, vf, mask, Cx);

    // output projection + residual, LN1
    hgemm<false, false, true, false><<<gD, blk, HG_SMEM>>>(
        Cx, wh + WOFF_O, wl + WOFF_O, nullptr, x, T1, nullptr, DIM, DIM, 1.0f);
    layernorm_kernel<<<TOK, blk>>>(T1, ln1_g, ln1_b, Hb);

    // FFN + residual, LN2
    hgemm<true, true, false, false><<<gDFF, blk, HG_SMEM>>>(
        Hb, wh + WOFF_W1, wl + WOFF_W1, b1, nullptr, Ff, nullptr, DFF, DIM, 1.0f);
    hgemm<true, false, true, false><<<gD, blk, HG_SMEM>>>(
        Ff, wh + WOFF_W2, wl + WOFF_W2, b2, Hb, T1, nullptr, DIM, DFF, 1.0f);
    layernorm_kernel<<<TOK, blk>>>(T1, ln2_g, ln2_b, out);
}